// round 2
// baseline (speedup 1.0000x reference)
#include <cuda_runtime.h>
#include <cuda_bf16.h>

// ---------------------------------------------------------------------------
// Conv_DCFD: conv1(3x3,128->64)+BN(H)+ReLU -> conv2(3x3,64->36)+BN(H)+ReLU
//            -> xFB[6,9] -> dyn[.,6,9] ; bases_out via SCRAMBLED patch reshape
//            -> 1x1 conv [768 -> 256] + bias
// Shapes: N=16,H=64,W=64,C=128, inter=64, bases=36, M=6, O=256
//
// Patch semantics (the trap): extract_patches gives flat depth f=(ki*3+kj)*128+cc,
// reference reshapes to [C,9] WITHOUT transpose: patch[c][l] = flat[c*9+l].
// ---------------------------------------------------------------------------

#define NB   16
#define HH   64
#define WW   64
#define CIN  128
#define CMID 64
#define BSZ  36
#define MM   6
#define OO   256

// scratch (no cudaMalloc allowed)
__device__ float g_h  [NB * HH * WW * CMID];   // 16.8 MB
__device__ float g_dyn[NB * HH * WW * 54];     // 14.2 MB

__device__ __forceinline__ void cp_async16(void* smem_dst, const void* gmem_src) {
    unsigned s = (unsigned)__cvta_generic_to_shared(smem_dst);
    asm volatile("cp.async.cg.shared.global [%0], [%1], 16;\n" :: "r"(s), "l"(gmem_src));
}
__device__ __forceinline__ void cp_commit() { asm volatile("cp.async.commit_group;\n"); }
template<int N> __device__ __forceinline__ void cp_wait() {
    asm volatile("cp.async.wait_group %0;\n" :: "n"(N));
}

// ===========================================================================
// Kernel 1: conv1 + BN(axis=H) + ReLU  -> g_h
// grid = N*H (1024), block = 256. One image row (64 px) x 64 out ch per block.
// ===========================================================================
#define K1_SLAB   (CIN * 201)         // 25728 floats
#define K1_WBUF   (CIN * CMID)        // 8192 floats per chunk
#define K1_SMEM   ((K1_SLAB + 2 * K1_WBUF) * 4)

__global__ __launch_bounds__(256, 1)
void conv1_kernel(const float* __restrict__ x, const float* __restrict__ w1,
                  const float* __restrict__ b1, const float* __restrict__ gamma1,
                  const float* __restrict__ beta1) {
    extern __shared__ float sm[];
    float* slab = sm;
    float* wbuf = sm + K1_SLAB;

    const int t  = threadIdx.x;
    const int bx = blockIdx.x;
    const int nb = bx >> 6;
    const int h  = bx & 63;

    // preload weight chunk 0 (kh=0,kw=0): [128ci][64co] contiguous
    for (int i = t; i < K1_WBUF / 4; i += 256)
        cp_async16(wbuf + i * 4, w1 + i * 4);
    cp_commit();

    // load x slab: rows h-1..h+1, cols -1..64, 128 ci (float4 over ci)
    const float4* x4 = (const float4*)x;
    for (int idx = t; idx < 3 * 66 * 32; idx += 256) {
        int ci4 = idx & 31;
        int col = (idx >> 5) % 66;
        int r   = idx / (32 * 66);
        int hh  = h + r - 1, ww = col - 1;
        float4 v = make_float4(0.f, 0.f, 0.f, 0.f);
        if (hh >= 0 && hh < HH && ww >= 0 && ww < WW)
            v = x4[((((nb << 6) + hh) << 6) + ww) * 32 + ci4];
        int so = r * 66 + col;
        slab[(ci4 * 4 + 0) * 201 + so] = v.x;
        slab[(ci4 * 4 + 1) * 201 + so] = v.y;
        slab[(ci4 * 4 + 2) * 201 + so] = v.z;
        slab[(ci4 * 4 + 3) * 201 + so] = v.w;
    }
    cp_wait<0>();
    __syncthreads();

    const int p0  = (t >> 4) << 2;   // pixel base (0..60)
    const int co0 = (t & 15) << 2;   // out-channel base (0..60)
    float acc[4][4] = {};

    for (int kk = 0; kk < 9; kk++) {
        const float* wb = wbuf + (kk & 1) * K1_WBUF;
        if (kk < 8) {
            const float* src = w1 + (kk + 1) * K1_WBUF;
            float* dst = wbuf + ((kk + 1) & 1) * K1_WBUF;
            for (int i = t; i < K1_WBUF / 4; i += 256)
                cp_async16(dst + i * 4, src + i * 4);
            cp_commit();
        }
        const int kh = kk / 3, kw = kk % 3;
        const int abase = kh * 66 + kw + p0;
        #pragma unroll 4
        for (int ci = 0; ci < CIN; ci++) {
            float a[4];
            #pragma unroll
            for (int i = 0; i < 4; i++) a[i] = slab[ci * 201 + abase + i];
            float4 wv = *(const float4*)(wb + (ci << 6) + co0);
            #pragma unroll
            for (int i = 0; i < 4; i++) {
                acc[i][0] = fmaf(a[i], wv.x, acc[i][0]);
                acc[i][1] = fmaf(a[i], wv.y, acc[i][1]);
                acc[i][2] = fmaf(a[i], wv.z, acc[i][2]);
                acc[i][3] = fmaf(a[i], wv.w, acc[i][3]);
            }
        }
        cp_wait<0>();
        __syncthreads();
    }

    const float invs = rsqrtf(1.0f + 1e-3f);
    const float gs = gamma1[h] * invs;
    const float bb = beta1[h];
    float4 bv = *(const float4*)(b1 + co0);
    float4* o4 = (float4*)g_h;
    #pragma unroll
    for (int i = 0; i < 4; i++) {
        float4 o;
        o.x = fmaxf(fmaf(acc[i][0] + bv.x, gs, bb), 0.f);
        o.y = fmaxf(fmaf(acc[i][1] + bv.y, gs, bb), 0.f);
        o.z = fmaxf(fmaf(acc[i][2] + bv.z, gs, bb), 0.f);
        o.w = fmaxf(fmaf(acc[i][3] + bv.w, gs, bb), 0.f);
        o4[(((bx << 6) + p0 + i) << 4) + (co0 >> 2)] = o;
    }
}

// ===========================================================================
// Kernel 2: conv2 + BN + ReLU + multiply by bases -> g_dyn [pix][6][9]
// grid = N*H/2 (512), block = 256. Two image rows (128 px) x 36 out.
// ===========================================================================
#define K2_SLAB  (CMID * 265)                 // 16960
#define K2_WS    (3 * 3 * CMID * BSZ)         // 20736
#define K2_BFS   (128 * 37)                   // 4736
#define K2_SMEM  ((K2_SLAB + K2_WS + K2_BFS + 56) * 4)

__global__ __launch_bounds__(256, 1)
void conv2_kernel(const float* __restrict__ w2, const float* __restrict__ b2,
                  const float* __restrict__ gamma2, const float* __restrict__ beta2,
                  const float* __restrict__ bases) {
    extern __shared__ float sm[];
    float* slab = sm;
    float* ws   = sm + K2_SLAB;
    float* bfs  = ws + K2_WS;
    float* bss  = bfs + K2_BFS;

    const int t  = threadIdx.x;
    const int bx = blockIdx.x;
    const int nb = bx >> 5;
    const int h0 = (bx & 31) << 1;

    // slab: rows h0-1..h0+2 (4), cols -1..64 (66), 64 ci
    const float4* hin4 = (const float4*)g_h;
    for (int idx = t; idx < 4 * 66 * 16; idx += 256) {
        int ci4 = idx & 15;
        int col = (idx >> 4) % 66;
        int r   = idx / (16 * 66);
        int hh  = h0 + r - 1, ww = col - 1;
        float4 v = make_float4(0.f, 0.f, 0.f, 0.f);
        if (hh >= 0 && hh < HH && ww >= 0 && ww < WW)
            v = hin4[((((nb << 6) + hh) << 6) + ww) * 16 + ci4];
        int so = r * 66 + col;
        slab[(ci4 * 4 + 0) * 265 + so] = v.x;
        slab[(ci4 * 4 + 1) * 265 + so] = v.y;
        slab[(ci4 * 4 + 2) * 265 + so] = v.z;
        slab[(ci4 * 4 + 3) * 265 + so] = v.w;
    }
    for (int i = t; i < K2_WS / 4; i += 256)
        ((float4*)ws)[i] = ((const float4*)w2)[i];
    if (t < 54) bss[t] = bases[t];
    __syncthreads();

    const int p  = t & 63;
    const int g  = t >> 6;       // 0..3
    const int co = g * 9;
    float acc0[9] = {}, acc1[9] = {};

    for (int kw = 0; kw < 3; kw++) {
        for (int ci = 0; ci < CMID; ci++) {
            float a[4];
            #pragma unroll
            for (int r = 0; r < 4; r++) a[r] = slab[ci * 265 + r * 66 + p + kw];
            #pragma unroll
            for (int kh = 0; kh < 3; kh++) {
                const float* wrow = ws + ((kh * 3 + kw) * CMID + ci) * BSZ + co;
                #pragma unroll
                for (int j = 0; j < 9; j++) {
                    float wv = wrow[j];
                    acc0[j] = fmaf(a[kh],     wv, acc0[j]);
                    acc1[j] = fmaf(a[kh + 1], wv, acc1[j]);
                }
            }
        }
    }

    const float invs = rsqrtf(1.0f + 1e-3f);
    const float gs0 = gamma2[h0] * invs,     bb0 = beta2[h0];
    const float gs1 = gamma2[h0 + 1] * invs, bb1 = beta2[h0 + 1];
    #pragma unroll
    for (int j = 0; j < 9; j++) {
        float bj = b2[co + j];
        bfs[(0 * 64 + p) * 37 + co + j] = fmaxf(fmaf(acc0[j] + bj, gs0, bb0), 0.f);
        bfs[(1 * 64 + p) * 37 + co + j] = fmaxf(fmaf(acc1[j] + bj, gs1, bb1), 0.f);
    }
    __syncthreads();

    // dyn[m][l] = sum_k bfeat[m*6+k] * bases[k][l]
    const int pp = t >> 1;          // 0..127
    const int half = t & 1;
    const float* bf = bfs + pp * 37;
    const int rr = pp >> 6, pw = pp & 63;
    float* outp = g_dyn + (size_t)((((nb << 6) + h0 + rr) << 6) + pw) * 54;
    #pragma unroll
    for (int q = 0; q < 27; q++) {
        int idx = half * 27 + q;
        int m = idx / 9, l = idx % 9;
        float s = 0.f;
        #pragma unroll
        for (int k = 0; k < 6; k++) s = fmaf(bf[m * 6 + k], bss[k * 9 + l], s);
        outp[idx] = s;
    }
}

// ===========================================================================
// Kernel 3: bases_out tile (with SCRAMBLED patch mapping) + GEMM + bias -> out
// grid = 65536/32 (2048), block = 256.
// As[p][c*6+m] = sum_l dyn[p][m][l] * flatpatch[p][c*9+l]
//   flatpatch[p][f] = xpad[h + f/384 - 1, w + (f/128)%3 - 1, f%128]
//                   = slab[(f%128)*103 + (f/384)*34 + (f/128)%3 + p]
// ===========================================================================
#define K3_SLAB  (CIN * 103)          // 13184
#define K3_DYN   (32 * 54)            // 1728
#define K3_AS    (32 * 769)           // 24608
#define K3_BS    (2 * 32 * OO)        // 16384
#define K3_OFF   1152
#define K3_SMEM  ((K3_SLAB + K3_DYN + K3_AS + K3_BS + K3_OFF) * 4)

__global__ __launch_bounds__(256, 1)
void fused_out_kernel(const float* __restrict__ x, const float* __restrict__ coef,
                      const float* __restrict__ bias, float* __restrict__ out) {
    extern __shared__ float sm[];
    float* slab = sm;
    float* dyns = slab + K3_SLAB;
    float* As   = dyns + K3_DYN;
    float* Bs   = As + K3_AS;
    int*   off  = (int*)(Bs + K3_BS);

    const int t  = threadIdx.x;
    const int bx = blockIdx.x;
    const int pix0 = bx << 5;
    const int nb = bx >> 7;
    const int h  = (bx >> 1) & 63;
    const int w0 = (bx & 1) << 5;

    // kick off B chunk 0 immediately
    for (int i = t; i < 2048; i += 256)
        cp_async16(Bs + i * 4, coef + i * 4);
    cp_commit();

    // flat-patch index -> slab offset table
    for (int f = t; f < 1152; f += 256) {
        int cc = f & 127;
        int pi = f >> 7;            // (ki*3 + kj), 0..8
        off[f] = cc * 103 + (pi / 3) * 34 + (pi % 3);
    }

    // x slab: rows h-1..h+1 (3), cols w0-1..w0+32 (34), 128 ci
    const float4* x4 = (const float4*)x;
    for (int idx = t; idx < 3 * 34 * 32; idx += 256) {
        int ci4 = idx & 31;
        int col = (idx >> 5) % 34;
        int r   = idx / (32 * 34);
        int hh  = h + r - 1, ww = w0 + col - 1;
        float4 v = make_float4(0.f, 0.f, 0.f, 0.f);
        if (hh >= 0 && hh < HH && ww >= 0 && ww < WW)
            v = x4[((((nb << 6) + hh) << 6) + ww) * 32 + ci4];
        int so = r * 34 + col;
        slab[(ci4 * 4 + 0) * 103 + so] = v.x;
        slab[(ci4 * 4 + 1) * 103 + so] = v.y;
        slab[(ci4 * 4 + 2) * 103 + so] = v.z;
        slab[(ci4 * 4 + 3) * 103 + so] = v.w;
    }
    for (int i = t; i < K3_DYN; i += 256)
        dyns[i] = g_dyn[(size_t)pix0 * 54 + i];
    __syncthreads();

    // stage 1: As[p][c*6+m] via scrambled patch mapping
    {
        const int p = t & 31, cg = t >> 5;
        float dv[54];
        #pragma unroll
        for (int i = 0; i < 54; i++) dv[i] = dyns[p * 54 + i];
        for (int c = cg * 16; c < cg * 16 + 16; c++) {
            float pt[9];
            #pragma unroll
            for (int l = 0; l < 9; l++) pt[l] = slab[off[c * 9 + l] + p];
            #pragma unroll
            for (int m = 0; m < 6; m++) {
                float s = 0.f;
                #pragma unroll
                for (int l = 0; l < 9; l++) s = fmaf(dv[m * 9 + l], pt[l], s);
                As[p * 769 + c * 6 + m] = s;
            }
        }
    }
    cp_wait<0>();
    __syncthreads();

    // stage 2: GEMM [32 x 768] x [768 x 256], Kc = 32, double-buffered
    const int tc = t & 31, tr = t >> 5;
    const int n0 = tc << 3, pr0 = tr << 2;
    float acc[4][8] = {};

    for (int kc = 0; kc < 24; kc++) {
        const float* Bc = Bs + (kc & 1) * (32 * OO);
        if (kc < 23) {
            const float* src = coef + (kc + 1) * (32 * OO);
            float* dst = Bs + ((kc + 1) & 1) * (32 * OO);
            for (int i = t; i < 2048; i += 256)
                cp_async16(dst + i * 4, src + i * 4);
            cp_commit();
        }
        const int kbase = kc * 32;
        #pragma unroll 8
        for (int kk = 0; kk < 32; kk++) {
            float a[4];
            #pragma unroll
            for (int i = 0; i < 4; i++) a[i] = As[(pr0 + i) * 769 + kbase + kk];
            float4 b0 = *(const float4*)(Bc + kk * OO + n0);
            float4 b1 = *(const float4*)(Bc + kk * OO + n0 + 4);
            #pragma unroll
            for (int i = 0; i < 4; i++) {
                acc[i][0] = fmaf(a[i], b0.x, acc[i][0]);
                acc[i][1] = fmaf(a[i], b0.y, acc[i][1]);
                acc[i][2] = fmaf(a[i], b0.z, acc[i][2]);
                acc[i][3] = fmaf(a[i], b0.w, acc[i][3]);
                acc[i][4] = fmaf(a[i], b1.x, acc[i][4]);
                acc[i][5] = fmaf(a[i], b1.y, acc[i][5]);
                acc[i][6] = fmaf(a[i], b1.z, acc[i][6]);
                acc[i][7] = fmaf(a[i], b1.w, acc[i][7]);
            }
        }
        cp_wait<0>();
        __syncthreads();
    }

    float4 bv0 = *(const float4*)(bias + n0);
    float4 bv1 = *(const float4*)(bias + n0 + 4);
    #pragma unroll
    for (int i = 0; i < 4; i++) {
        float4 o0, o1;
        o0.x = acc[i][0] + bv0.x; o0.y = acc[i][1] + bv0.y;
        o0.z = acc[i][2] + bv0.z; o0.w = acc[i][3] + bv0.w;
        o1.x = acc[i][4] + bv1.x; o1.y = acc[i][5] + bv1.y;
        o1.z = acc[i][6] + bv1.z; o1.w = acc[i][7] + bv1.w;
        float* op = out + (size_t)(pix0 + pr0 + i) * OO + n0;
        *(float4*)op = o0;
        *(float4*)(op + 4) = o1;
    }
}

// ===========================================================================
extern "C" void kernel_launch(void* const* d_in, const int* in_sizes, int n_in,
                              void* d_out, int out_size) {
    const float* x      = (const float*)d_in[0];
    const float* w1     = (const float*)d_in[1];
    const float* b1     = (const float*)d_in[2];
    const float* gamma1 = (const float*)d_in[3];
    const float* beta1  = (const float*)d_in[4];
    const float* w2     = (const float*)d_in[5];
    const float* b2     = (const float*)d_in[6];
    const float* gamma2 = (const float*)d_in[7];
    const float* beta2  = (const float*)d_in[8];
    const float* bases  = (const float*)d_in[9];
    const float* coef   = (const float*)d_in[10];
    const float* bias   = (const float*)d_in[11];
    float* out = (float*)d_out;

    cudaFuncSetAttribute(conv1_kernel,     cudaFuncAttributeMaxDynamicSharedMemorySize, K1_SMEM);
    cudaFuncSetAttribute(conv2_kernel,     cudaFuncAttributeMaxDynamicSharedMemorySize, K2_SMEM);
    cudaFuncSetAttribute(fused_out_kernel, cudaFuncAttributeMaxDynamicSharedMemorySize, K3_SMEM);

    conv1_kernel    <<<NB * HH,     256, K1_SMEM>>>(x, w1, b1, gamma1, beta1);
    conv2_kernel    <<<NB * HH / 2, 256, K2_SMEM>>>(w2, b2, gamma2, beta2, bases);
    fused_out_kernel<<<NB * HH * WW / 32, 256, K3_SMEM>>>(x, coef, bias, out);
}

// round 4
// speedup vs baseline: 1.7838x; 1.7838x over previous
#include <cuda_runtime.h>
#include <cuda_bf16.h>
#include <cstdint>

// ---------------------------------------------------------------------------
// Conv_DCFD: conv1(3x3,128->64)+BN(H)+ReLU -> conv2(3x3,64->36)+BN(H)+ReLU
//            -> xFB[6,9] -> dyn ; bases_out via SCRAMBLED patch reshape
//            -> 1x1 conv [768 -> 256] + bias  (mma.sync tf32 tensor GEMM;
//               tcgen05 unavailable: harness compiles -arch=sm_100, no 'a')
// Shapes: N=16,H=64,W=64,C=128, inter=64, bases=36, M=6, O=256
// ---------------------------------------------------------------------------

#define NB   16
#define HH   64
#define WW   64
#define CIN  128
#define CMID 64
#define BSZ  36
#define OO   256

// scratch (no cudaMalloc allowed)
__device__ float g_h  [NB * HH * WW * CMID];      // 16.8 MB
__device__ float g_dyn[NB * HH * WW * 54];        // 14.2 MB
__device__ float g_A  [NB * HH * WW * 768];       // 201 MB (tf32-rounded, row-major)
__device__ float g_Bt [OO * 768];                 // 768 KB (B^T rows, tf32-rounded)

__device__ __forceinline__ void cp_async16(void* smem_dst, const void* gmem_src) {
    unsigned s = (unsigned)__cvta_generic_to_shared(smem_dst);
    asm volatile("cp.async.cg.shared.global [%0], [%1], 16;\n" :: "r"(s), "l"(gmem_src));
}
__device__ __forceinline__ void cp_commit() { asm volatile("cp.async.commit_group;\n"); }
template<int N> __device__ __forceinline__ void cp_wait() {
    asm volatile("cp.async.wait_group %0;\n" :: "n"(N));
}
__device__ __forceinline__ uint32_t tf32_rna(float v) {
    uint32_t r;
    asm("cvt.rna.tf32.f32 %0, %1;" : "=r"(r) : "f"(v));
    return r;
}
__device__ __forceinline__ void mma_tf32(float* d, const uint32_t* a, const uint32_t* b) {
    asm volatile(
        "mma.sync.aligned.m16n8k8.row.col.f32.tf32.tf32.f32 "
        "{%0,%1,%2,%3}, {%4,%5,%6,%7}, {%8,%9}, {%0,%1,%2,%3};"
        : "+f"(d[0]), "+f"(d[1]), "+f"(d[2]), "+f"(d[3])
        : "r"(a[0]), "r"(a[1]), "r"(a[2]), "r"(a[3]), "r"(b[0]), "r"(b[1]));
}

// ===========================================================================
// Kernel 1: conv1 + BN(axis=H) + ReLU  -> g_h       (unchanged, passing)
// ===========================================================================
#define K1_SLAB   (CIN * 201)
#define K1_WBUF   (CIN * CMID)
#define K1_SMEM   ((K1_SLAB + 2 * K1_WBUF) * 4)

__global__ __launch_bounds__(256, 1)
void conv1_kernel(const float* __restrict__ x, const float* __restrict__ w1,
                  const float* __restrict__ b1, const float* __restrict__ gamma1,
                  const float* __restrict__ beta1) {
    extern __shared__ float sm[];
    float* slab = sm;
    float* wbuf = sm + K1_SLAB;

    const int t  = threadIdx.x;
    const int bx = blockIdx.x;
    const int nb = bx >> 6;
    const int h  = bx & 63;

    for (int i = t; i < K1_WBUF / 4; i += 256)
        cp_async16(wbuf + i * 4, w1 + i * 4);
    cp_commit();

    const float4* x4 = (const float4*)x;
    for (int idx = t; idx < 3 * 66 * 32; idx += 256) {
        int ci4 = idx & 31;
        int col = (idx >> 5) % 66;
        int r   = idx / (32 * 66);
        int hh  = h + r - 1, ww = col - 1;
        float4 v = make_float4(0.f, 0.f, 0.f, 0.f);
        if (hh >= 0 && hh < HH && ww >= 0 && ww < WW)
            v = x4[((((nb << 6) + hh) << 6) + ww) * 32 + ci4];
        int so = r * 66 + col;
        slab[(ci4 * 4 + 0) * 201 + so] = v.x;
        slab[(ci4 * 4 + 1) * 201 + so] = v.y;
        slab[(ci4 * 4 + 2) * 201 + so] = v.z;
        slab[(ci4 * 4 + 3) * 201 + so] = v.w;
    }
    cp_wait<0>();
    __syncthreads();

    const int p0  = (t >> 4) << 2;
    const int co0 = (t & 15) << 2;
    float acc[4][4] = {};

    for (int kk = 0; kk < 9; kk++) {
        const float* wb = wbuf + (kk & 1) * K1_WBUF;
        if (kk < 8) {
            const float* src = w1 + (kk + 1) * K1_WBUF;
            float* dst = wbuf + ((kk + 1) & 1) * K1_WBUF;
            for (int i = t; i < K1_WBUF / 4; i += 256)
                cp_async16(dst + i * 4, src + i * 4);
            cp_commit();
        }
        const int kh = kk / 3, kw = kk % 3;
        const int abase = kh * 66 + kw + p0;
        #pragma unroll 4
        for (int ci = 0; ci < CIN; ci++) {
            float a[4];
            #pragma unroll
            for (int i = 0; i < 4; i++) a[i] = slab[ci * 201 + abase + i];
            float4 wv = *(const float4*)(wb + (ci << 6) + co0);
            #pragma unroll
            for (int i = 0; i < 4; i++) {
                acc[i][0] = fmaf(a[i], wv.x, acc[i][0]);
                acc[i][1] = fmaf(a[i], wv.y, acc[i][1]);
                acc[i][2] = fmaf(a[i], wv.z, acc[i][2]);
                acc[i][3] = fmaf(a[i], wv.w, acc[i][3]);
            }
        }
        cp_wait<0>();
        __syncthreads();
    }

    const float invs = rsqrtf(1.0f + 1e-3f);
    const float gs = gamma1[h] * invs;
    const float bb = beta1[h];
    float4 bv = *(const float4*)(b1 + co0);
    float4* o4 = (float4*)g_h;
    #pragma unroll
    for (int i = 0; i < 4; i++) {
        float4 o;
        o.x = fmaxf(fmaf(acc[i][0] + bv.x, gs, bb), 0.f);
        o.y = fmaxf(fmaf(acc[i][1] + bv.y, gs, bb), 0.f);
        o.z = fmaxf(fmaf(acc[i][2] + bv.z, gs, bb), 0.f);
        o.w = fmaxf(fmaf(acc[i][3] + bv.w, gs, bb), 0.f);
        o4[(((bx << 6) + p0 + i) << 4) + (co0 >> 2)] = o;
    }
}

// ===========================================================================
// Kernel 2: conv2 + BN + ReLU + xFB -> g_dyn        (unchanged, passing)
// ===========================================================================
#define K2_SLAB  (CMID * 265)
#define K2_WS    (3 * 3 * CMID * BSZ)
#define K2_BFS   (128 * 37)
#define K2_SMEM  ((K2_SLAB + K2_WS + K2_BFS + 56) * 4)

__global__ __launch_bounds__(256, 1)
void conv2_kernel(const float* __restrict__ w2, const float* __restrict__ b2,
                  const float* __restrict__ gamma2, const float* __restrict__ beta2,
                  const float* __restrict__ bases) {
    extern __shared__ float sm[];
    float* slab = sm;
    float* ws   = sm + K2_SLAB;
    float* bfs  = ws + K2_WS;
    float* bss  = bfs + K2_BFS;

    const int t  = threadIdx.x;
    const int bx = blockIdx.x;
    const int nb = bx >> 5;
    const int h0 = (bx & 31) << 1;

    const float4* hin4 = (const float4*)g_h;
    for (int idx = t; idx < 4 * 66 * 16; idx += 256) {
        int ci4 = idx & 15;
        int col = (idx >> 4) % 66;
        int r   = idx / (16 * 66);
        int hh  = h0 + r - 1, ww = col - 1;
        float4 v = make_float4(0.f, 0.f, 0.f, 0.f);
        if (hh >= 0 && hh < HH && ww >= 0 && ww < WW)
            v = hin4[((((nb << 6) + hh) << 6) + ww) * 16 + ci4];
        int so = r * 66 + col;
        slab[(ci4 * 4 + 0) * 265 + so] = v.x;
        slab[(ci4 * 4 + 1) * 265 + so] = v.y;
        slab[(ci4 * 4 + 2) * 265 + so] = v.z;
        slab[(ci4 * 4 + 3) * 265 + so] = v.w;
    }
    for (int i = t; i < K2_WS / 4; i += 256)
        ((float4*)ws)[i] = ((const float4*)w2)[i];
    if (t < 54) bss[t] = bases[t];
    __syncthreads();

    const int p  = t & 63;
    const int g  = t >> 6;
    const int co = g * 9;
    float acc0[9] = {}, acc1[9] = {};

    for (int kw = 0; kw < 3; kw++) {
        for (int ci = 0; ci < CMID; ci++) {
            float a[4];
            #pragma unroll
            for (int r = 0; r < 4; r++) a[r] = slab[ci * 265 + r * 66 + p + kw];
            #pragma unroll
            for (int kh = 0; kh < 3; kh++) {
                const float* wrow = ws + ((kh * 3 + kw) * CMID + ci) * BSZ + co;
                #pragma unroll
                for (int j = 0; j < 9; j++) {
                    float wv = wrow[j];
                    acc0[j] = fmaf(a[kh],     wv, acc0[j]);
                    acc1[j] = fmaf(a[kh + 1], wv, acc1[j]);
                }
            }
        }
    }

    const float invs = rsqrtf(1.0f + 1e-3f);
    const float gs0 = gamma2[h0] * invs,     bb0 = beta2[h0];
    const float gs1 = gamma2[h0 + 1] * invs, bb1 = beta2[h0 + 1];
    #pragma unroll
    for (int j = 0; j < 9; j++) {
        float bj = b2[co + j];
        bfs[(0 * 64 + p) * 37 + co + j] = fmaxf(fmaf(acc0[j] + bj, gs0, bb0), 0.f);
        bfs[(1 * 64 + p) * 37 + co + j] = fmaxf(fmaf(acc1[j] + bj, gs1, bb1), 0.f);
    }
    __syncthreads();

    const int pp = t >> 1;
    const int half = t & 1;
    const float* bf = bfs + pp * 37;
    const int rr = pp >> 6, pw = pp & 63;
    float* outp = g_dyn + (size_t)((((nb << 6) + h0 + rr) << 6) + pw) * 54;
    #pragma unroll
    for (int q = 0; q < 27; q++) {
        int idx = half * 27 + q;
        int m = idx / 9, l = idx % 9;
        float s = 0.f;
        #pragma unroll
        for (int k = 0; k < 6; k++) s = fmaf(bf[m * 6 + k], bss[k * 9 + l], s);
        outp[idx] = s;
    }
}

// ===========================================================================
// prepB: g_Bt[n][k] = tf32_rna(coef[k][n]); grid 256, block 256
// ===========================================================================
__global__ void prepB_kernel(const float* __restrict__ coef) {
    const int n = blockIdx.x;
    const int t = threadIdx.x;
    #pragma unroll
    for (int q = 0; q < 3; q++) {
        int k = q * 256 + t;
        g_Bt[n * 768 + k] = __uint_as_float(tf32_rna(coef[k * OO + n]));
    }
}

// ===========================================================================
// Kernel 3a: bases_out A -> g_A[65536][768] (tf32-rounded, coalesced stores)
// grid = 512 (mt = 2 image rows), block = 256 (8 warps).
// Warp handles 16 pixels; lane covers channels lane*4..+3 -> k = lane*24..+23
// As[p][k=c*6+m] = sum_l dyn[p][m][l]*flatpatch[p][c*9+l], scrambled mapping:
//   f=c*9+l -> cc=f&127, pi=f>>7; slab offset = cc*265 + (pi/3)*66 + (pi%3)
// ===========================================================================
#define K3A_SLAB (CIN * 265)          // 33920 floats
#define K3A_DYN  (128 * 54)           // 6912
#define K3A_OFF  1152
#define K3A_SMEM ((K3A_SLAB + K3A_DYN + K3A_OFF) * 4)

__global__ __launch_bounds__(256, 1)
void k3a_kernel(const float* __restrict__ x) {
    extern __shared__ float sm[];
    float* slab = sm;
    float* dyns = slab + K3A_SLAB;
    int*   off  = (int*)(dyns + K3A_DYN);

    const int t  = threadIdx.x;
    const int mt = blockIdx.x;
    const int nb = mt >> 5;
    const int h0 = (mt & 31) << 1;

    for (int f = t; f < 1152; f += 256) {
        int cc = f & 127;
        int pi = f >> 7;
        off[f] = cc * 265 + (pi / 3) * 66 + (pi % 3);
    }

    // x slab: rows h0-1..h0+2 (4), cols -1..64 (66), 128 ci
    const float4* x4 = (const float4*)x;
    for (int idx = t; idx < 4 * 66 * 32; idx += 256) {
        int ci4 = idx & 31;
        int col = (idx >> 5) % 66;
        int r   = idx / (32 * 66);
        int hh  = h0 + r - 1, ww = col - 1;
        float4 v = make_float4(0.f, 0.f, 0.f, 0.f);
        if (hh >= 0 && hh < HH && ww >= 0 && ww < WW)
            v = x4[((((nb << 6) + hh) << 6) + ww) * 32 + ci4];
        int so = r * 66 + col;
        slab[(ci4 * 4 + 0) * 265 + so] = v.x;
        slab[(ci4 * 4 + 1) * 265 + so] = v.y;
        slab[(ci4 * 4 + 2) * 265 + so] = v.z;
        slab[(ci4 * 4 + 3) * 265 + so] = v.w;
    }
    {
        const size_t pixbase = (size_t)(((nb << 6) + h0) << 6) * 54;
        for (int i = t; i < K3A_DYN; i += 256)
            dyns[i] = g_dyn[pixbase + i];
    }
    __syncthreads();

    const int w    = t >> 5;
    const int lane = t & 31;

    for (int pp = 0; pp < 16; pp++) {
        const int p = (w << 4) + pp;
        const int padd = (p >> 6) * 66 + (p & 63);
        const float* dp = dyns + p * 54;
        float dv[54];
        #pragma unroll
        for (int i = 0; i < 54; i++) dv[i] = dp[i];   // warp-uniform broadcast

        uint32_t outv[24];
        #pragma unroll
        for (int j = 0; j < 4; j++) {
            const int ch = (lane << 2) + j;
            float pt[9];
            #pragma unroll
            for (int l = 0; l < 9; l++) pt[l] = slab[off[ch * 9 + l] + padd];
            #pragma unroll
            for (int m = 0; m < 6; m++) {
                float s = 0.f;
                #pragma unroll
                for (int l = 0; l < 9; l++) s = fmaf(dv[m * 9 + l], pt[l], s);
                outv[j * 6 + m] = tf32_rna(s);
            }
        }
        float4* dst = (float4*)(g_A + (size_t)((mt << 7) + p) * 768 + lane * 24);
        #pragma unroll
        for (int q = 0; q < 6; q++) dst[q] = ((const float4*)outv)[q];
    }
}

// ===========================================================================
// Kernel 3b: mma.sync tf32 GEMM out[65536,256] = A x B^T + bias
// grid 1024 (mt = bx>>1, nt = bx&1), block 256 (8 warps, 4x2 warp grid).
// Block tile 128x128; warp tile 32x64; K chunks of 32, double-buffered.
// smem chunk layout: [row][k] stride 36 floats (144B, 16B-aligned).
// ===========================================================================
#define K3B_STR  36
#define K3B_CHNK (128 * K3B_STR)                 // 4608 floats
#define K3B_SMEM (4 * K3B_CHNK * 4)              // 73728 bytes

__global__ __launch_bounds__(256, 1)
void k3b_kernel(const float* __restrict__ bias, float* __restrict__ out) {
    extern __shared__ float sm[];
    float* As[2] = { sm,                sm + K3B_CHNK };
    float* Bs[2] = { sm + 2 * K3B_CHNK, sm + 3 * K3B_CHNK };

    const int t    = threadIdx.x;
    const int bx   = blockIdx.x;
    const int mt   = bx >> 1;
    const int nt   = bx & 1;
    const int wid  = t >> 5;
    const int lane = t & 31;
    const int g    = lane >> 2;      // groupID
    const int tid4 = lane & 3;       // threadID in group

    const float* Abase = g_A  + (size_t)(mt << 7) * 768;
    const float* Bbase = g_Bt + (size_t)(nt << 7) * 768;

    // preload chunk 0
    {
        for (int i = t; i < 1024; i += 256) {
            int row = i >> 3, seg = i & 7;
            cp_async16(As[0] + row * K3B_STR + seg * 4, Abase + row * 768 + seg * 4);
            cp_async16(Bs[0] + row * K3B_STR + seg * 4, Bbase + row * 768 + seg * 4);
        }
        cp_commit();
    }

    const int wm = wid >> 1, wn = wid & 1;
    const int m0 = wm << 5, n0 = wn << 6;
    float d[2][8][4] = {};

    for (int kc = 0; kc < 24; kc++) {
        cp_wait<0>();
        __syncthreads();
        if (kc < 23) {
            const int nc = kc + 1, buf = nc & 1;
            const float* as = Abase + nc * 32;
            const float* bs = Bbase + nc * 32;
            for (int i = t; i < 1024; i += 256) {
                int row = i >> 3, seg = i & 7;
                cp_async16(As[buf] + row * K3B_STR + seg * 4, as + row * 768 + seg * 4);
                cp_async16(Bs[buf] + row * K3B_STR + seg * 4, bs + row * 768 + seg * 4);
            }
            cp_commit();
        }
        const float* Ac = As[kc & 1];
        const float* Bc = Bs[kc & 1];

        #pragma unroll
        for (int kt = 0; kt < 4; kt++) {
            const int k0 = kt << 3;
            uint32_t a[2][4], b[8][2];
            #pragma unroll
            for (int mi = 0; mi < 2; mi++) {
                const float* ap = Ac + (m0 + (mi << 4) + g) * K3B_STR + k0 + tid4;
                a[mi][0] = __float_as_uint(ap[0]);
                a[mi][1] = __float_as_uint(ap[8 * K3B_STR]);
                a[mi][2] = __float_as_uint(ap[4]);
                a[mi][3] = __float_as_uint(ap[8 * K3B_STR + 4]);
            }
            #pragma unroll
            for (int ni = 0; ni < 8; ni++) {
                const float* bp = Bc + (n0 + (ni << 3) + g) * K3B_STR + k0 + tid4;
                b[ni][0] = __float_as_uint(bp[0]);
                b[ni][1] = __float_as_uint(bp[4]);
            }
            #pragma unroll
            for (int mi = 0; mi < 2; mi++)
                #pragma unroll
                for (int ni = 0; ni < 8; ni++)
                    mma_tf32(d[mi][ni], a[mi], b[ni]);
        }
        __syncthreads();
    }

    // epilogue: d[mi][ni][0..3] -> out rows (mt*128 + m0 + mi*16 + g / +8),
    // cols nt*128 + n0 + ni*8 + tid4*2 (+1)
    const size_t rbase = (size_t)(mt << 7) + m0;
    const int    cbase = (nt << 7) + n0 + (tid4 << 1);
    #pragma unroll
    for (int mi = 0; mi < 2; mi++) {
        float* r0 = out + (rbase + (mi << 4) + g) * OO;
        float* r1 = r0 + 8 * OO;
        #pragma unroll
        for (int ni = 0; ni < 8; ni++) {
            const int c = cbase + (ni << 3);
            const float b0 = bias[c], b1 = bias[c + 1];
            float2 v0 = make_float2(d[mi][ni][0] + b0, d[mi][ni][1] + b1);
            float2 v1 = make_float2(d[mi][ni][2] + b0, d[mi][ni][3] + b1);
            *(float2*)(r0 + c) = v0;
            *(float2*)(r1 + c) = v1;
        }
    }
}

// ===========================================================================
extern "C" void kernel_launch(void* const* d_in, const int* in_sizes, int n_in,
                              void* d_out, int out_size) {
    const float* x      = (const float*)d_in[0];
    const float* w1     = (const float*)d_in[1];
    const float* b1     = (const float*)d_in[2];
    const float* gamma1 = (const float*)d_in[3];
    const float* beta1  = (const float*)d_in[4];
    const float* w2     = (const float*)d_in[5];
    const float* b2     = (const float*)d_in[6];
    const float* gamma2 = (const float*)d_in[7];
    const float* beta2  = (const float*)d_in[8];
    const float* bases  = (const float*)d_in[9];
    const float* coef   = (const float*)d_in[10];
    const float* bias   = (const float*)d_in[11];
    float* out = (float*)d_out;

    cudaFuncSetAttribute(conv1_kernel, cudaFuncAttributeMaxDynamicSharedMemorySize, K1_SMEM);
    cudaFuncSetAttribute(conv2_kernel, cudaFuncAttributeMaxDynamicSharedMemorySize, K2_SMEM);
    cudaFuncSetAttribute(k3a_kernel,   cudaFuncAttributeMaxDynamicSharedMemorySize, K3A_SMEM);
    cudaFuncSetAttribute(k3b_kernel,   cudaFuncAttributeMaxDynamicSharedMemorySize, K3B_SMEM);

    prepB_kernel<<<OO, 256>>>(coef);
    conv1_kernel<<<NB * HH,     256, K1_SMEM>>>(x, w1, b1, gamma1, beta1);
    conv2_kernel<<<NB * HH / 2, 256, K2_SMEM>>>(w2, b2, gamma2, beta2, bases);
    k3a_kernel  <<<512,         256, K3A_SMEM>>>(x);
    k3b_kernel  <<<1024,        256, K3B_SMEM>>>(bias, out);
}

// round 7
// speedup vs baseline: 2.5033x; 1.4033x over previous
#include <cuda_runtime.h>
#include <cuda_bf16.h>
#include <cstdint>

// ---------------------------------------------------------------------------
// Conv_DCFD on sm_100 (no tcgen05 in this toolchain): conv1 and the final
// 1x1 GEMM run on the legacy tensor pipe via mma.sync tf32 (rna-rounded).
// Shapes: N=16,H=64,W=64,C=128, inter=64, bases=36, M=6, O=256
// ---------------------------------------------------------------------------

#define NB   16
#define HH   64
#define WW   64
#define CIN  128
#define CMID 64
#define BSZ  36
#define OO   256

// scratch (no cudaMalloc allowed)
__device__ float g_h   [NB * HH * WW * CMID];     // 16.8 MB
__device__ float g_dyn [NB * HH * WW * 54];       // 14.2 MB
__device__ float g_A   [NB * HH * WW * 768];      // 201 MB (tf32-rounded)
__device__ float g_Bt  [OO * 768];                // 768 KB (B^T, tf32-rounded)
__device__ float g_W1t [9 * CMID * CIN];          // 295 KB (w1^T per tap, tf32)

__device__ __forceinline__ void cp_async16(void* smem_dst, const void* gmem_src) {
    unsigned s = (unsigned)__cvta_generic_to_shared(smem_dst);
    asm volatile("cp.async.cg.shared.global [%0], [%1], 16;\n" :: "r"(s), "l"(gmem_src));
}
__device__ __forceinline__ void cp_commit() { asm volatile("cp.async.commit_group;\n"); }
template<int N> __device__ __forceinline__ void cp_wait() {
    asm volatile("cp.async.wait_group %0;\n" :: "n"(N));
}
__device__ __forceinline__ uint32_t tf32_rna(float v) {
    uint32_t r;
    asm("cvt.rna.tf32.f32 %0, %1;" : "=r"(r) : "f"(v));
    return r;
}
__device__ __forceinline__ void mma_tf32(float* d, const uint32_t* a, const uint32_t* b) {
    asm volatile(
        "mma.sync.aligned.m16n8k8.row.col.f32.tf32.tf32.f32 "
        "{%0,%1,%2,%3}, {%4,%5,%6,%7}, {%8,%9}, {%0,%1,%2,%3};"
        : "+f"(d[0]), "+f"(d[1]), "+f"(d[2]), "+f"(d[3])
        : "r"(a[0]), "r"(a[1]), "r"(a[2]), "r"(a[3]), "r"(b[0]), "r"(b[1]));
}

// ===========================================================================
// prepW: g_W1t[(kk*64+co)*128+ci] = rna(w1[kk][ci][co])
// ===========================================================================
__global__ void prepW_kernel(const float* __restrict__ w1) {
    const int bx = blockIdx.x;          // kk*64+co (576)
    const int t  = threadIdx.x;         // ci (128)
    const int kk = bx >> 6, co = bx & 63;
    g_W1t[bx * 128 + t] = __uint_as_float(tf32_rna(w1[(kk * 128 + t) * 64 + co]));
}

// ===========================================================================
// prepB: g_Bt[n][k] = rna(coef[k][n])
// ===========================================================================
__global__ void prepB_kernel(const float* __restrict__ coef) {
    const int n = blockIdx.x;
    const int t = threadIdx.x;
    #pragma unroll
    for (int q = 0; q < 3; q++) {
        int k = q * 256 + t;
        g_Bt[n * 768 + k] = __uint_as_float(tf32_rna(coef[k * OO + n]));
    }
}

// ===========================================================================
// Kernel 1: conv1 via mma.sync tf32 + BN(axis=H) + ReLU -> g_h
// grid = 1024 (nb,h), block 256 (8 warps, 2m x 4n), warp tile 32px x 16co.
// slab [row66 = kh*66+(w+1)][ci] stride 132 (A row-major frags, conflict-free)
// wbuf [co][ci] stride 140, double-buffered cp.async from g_W1t.
// NOTE: weight chunk rows are 128 floats = 32 float4 segs -> 2048 cp.asyncs.
// ===========================================================================
#define C1_SSTR  132
#define C1_SLAB  (198 * C1_SSTR)        // 26136 floats
#define C1_WSTR  140
#define C1_WCH   (CMID * C1_WSTR)       // 8960 floats
#define C1_SMEM  ((C1_SLAB + 2 * C1_WCH) * 4)   // 176224 B

__global__ __launch_bounds__(256, 1)
void conv1_kernel(const float* __restrict__ x, const float* __restrict__ b1,
                  const float* __restrict__ gamma1, const float* __restrict__ beta1) {
    extern __shared__ float sm[];
    float* slab = sm;
    float* wbuf = sm + C1_SLAB;

    const int t  = threadIdx.x;
    const int bx = blockIdx.x;
    const int nb = bx >> 6;
    const int h  = bx & 63;

    // preload weight chunk 0 (64 co rows x 128 ci = 2048 float4 segments)
    for (int i = t; i < 2048; i += 256) {
        int row = i >> 5, seg = i & 31;
        cp_async16(wbuf + row * C1_WSTR + seg * 4, g_W1t + row * 128 + seg * 4);
    }
    cp_commit();

    // slab: rows h-1..h+1 (3), cols -1..64 (66), 128 ci, tf32-rounded
    const float4* x4 = (const float4*)x;
    for (int idx = t; idx < 3 * 66 * 32; idx += 256) {
        int ci4 = idx & 31;
        int col = (idx >> 5) % 66;
        int r   = idx / (32 * 66);
        int hh  = h + r - 1, ww = col - 1;
        float4 v = make_float4(0.f, 0.f, 0.f, 0.f);
        if (hh >= 0 && hh < HH && ww >= 0 && ww < WW)
            v = x4[((((nb << 6) + hh) << 6) + ww) * 32 + ci4];
        float4 o;
        o.x = __uint_as_float(tf32_rna(v.x));
        o.y = __uint_as_float(tf32_rna(v.y));
        o.z = __uint_as_float(tf32_rna(v.z));
        o.w = __uint_as_float(tf32_rna(v.w));
        *(float4*)(slab + (r * 66 + col) * C1_SSTR + ci4 * 4) = o;
    }
    cp_wait<0>();
    __syncthreads();

    const int wid  = t >> 5;
    const int lane = t & 31;
    const int g    = lane >> 2;
    const int t4   = lane & 3;
    const int wm   = wid >> 2;           // 0..1  (32-px group)
    const int wn   = wid & 3;            // 0..3  (16-co group)
    const int prow = wm << 5;

    float d[2][2][4] = {};

    for (int kk = 0; kk < 9; kk++) {
        const float* wb = wbuf + (kk & 1) * C1_WCH;
        if (kk < 8) {
            float* dst = wbuf + ((kk + 1) & 1) * C1_WCH;
            const float* src = g_W1t + (kk + 1) * 8192;
            for (int i = t; i < 2048; i += 256) {
                int row = i >> 5, seg = i & 31;
                cp_async16(dst + row * C1_WSTR + seg * 4, src + row * 128 + seg * 4);
            }
            cp_commit();
        }
        const int kh = kk / 3, kw = kk % 3;
        const float* arow = slab + (kh * 66 + kw + prow + g) * C1_SSTR;

        #pragma unroll
        for (int kt = 0; kt < 16; kt++) {
            const int k0 = kt << 3;
            uint32_t a[2][4], b[2][2];
            #pragma unroll
            for (int mi = 0; mi < 2; mi++) {
                const float* ap = arow + (mi << 4) * C1_SSTR + k0 + t4;
                a[mi][0] = __float_as_uint(ap[0]);
                a[mi][1] = __float_as_uint(ap[8 * C1_SSTR]);
                a[mi][2] = __float_as_uint(ap[4]);
                a[mi][3] = __float_as_uint(ap[8 * C1_SSTR + 4]);
            }
            #pragma unroll
            for (int ni = 0; ni < 2; ni++) {
                const float* bp = wb + ((wn << 4) + (ni << 3) + g) * C1_WSTR + k0 + t4;
                b[ni][0] = __float_as_uint(bp[0]);
                b[ni][1] = __float_as_uint(bp[4]);
            }
            #pragma unroll
            for (int mi = 0; mi < 2; mi++)
                #pragma unroll
                for (int ni = 0; ni < 2; ni++)
                    mma_tf32(d[mi][ni], a[mi], b[ni]);
        }
        cp_wait<0>();
        __syncthreads();
    }

    // epilogue: BN(axis=H) + ReLU + bias
    const float invs = rsqrtf(1.0f + 1e-3f);
    const float gs = gamma1[h] * invs;
    const float bb = beta1[h];
    #pragma unroll
    for (int mi = 0; mi < 2; mi++) {
        const int p0 = prow + (mi << 4) + g;
        float* r0 = g_h + ((size_t)(bx << 6) + p0) * CMID;
        float* r1 = r0 + 8 * CMID;
        #pragma unroll
        for (int ni = 0; ni < 2; ni++) {
            const int c = (wn << 4) + (ni << 3) + (t4 << 1);
            const float bc0 = b1[c], bc1 = b1[c + 1];
            float2 v0, v1;
            v0.x = fmaxf(fmaf(d[mi][ni][0] + bc0, gs, bb), 0.f);
            v0.y = fmaxf(fmaf(d[mi][ni][1] + bc1, gs, bb), 0.f);
            v1.x = fmaxf(fmaf(d[mi][ni][2] + bc0, gs, bb), 0.f);
            v1.y = fmaxf(fmaf(d[mi][ni][3] + bc1, gs, bb), 0.f);
            *(float2*)(r0 + c) = v0;
            *(float2*)(r1 + c) = v1;
        }
    }
}

// ===========================================================================
// Kernel 2: conv2 + BN + ReLU + xFB -> g_dyn        (unchanged, passing)
// ===========================================================================
#define K2_SLAB  (CMID * 265)
#define K2_WS    (3 * 3 * CMID * BSZ)
#define K2_BFS   (128 * 37)
#define K2_SMEM  ((K2_SLAB + K2_WS + K2_BFS + 56) * 4)

__global__ __launch_bounds__(256, 1)
void conv2_kernel(const float* __restrict__ w2, const float* __restrict__ b2,
                  const float* __restrict__ gamma2, const float* __restrict__ beta2,
                  const float* __restrict__ bases) {
    extern __shared__ float sm[];
    float* slab = sm;
    float* ws   = sm + K2_SLAB;
    float* bfs  = ws + K2_WS;
    float* bss  = bfs + K2_BFS;

    const int t  = threadIdx.x;
    const int bx = blockIdx.x;
    const int nb = bx >> 5;
    const int h0 = (bx & 31) << 1;

    const float4* hin4 = (const float4*)g_h;
    for (int idx = t; idx < 4 * 66 * 16; idx += 256) {
        int ci4 = idx & 15;
        int col = (idx >> 4) % 66;
        int r   = idx / (16 * 66);
        int hh  = h0 + r - 1, ww = col - 1;
        float4 v = make_float4(0.f, 0.f, 0.f, 0.f);
        if (hh >= 0 && hh < HH && ww >= 0 && ww < WW)
            v = hin4[((((nb << 6) + hh) << 6) + ww) * 16 + ci4];
        int so = r * 66 + col;
        slab[(ci4 * 4 + 0) * 265 + so] = v.x;
        slab[(ci4 * 4 + 1) * 265 + so] = v.y;
        slab[(ci4 * 4 + 2) * 265 + so] = v.z;
        slab[(ci4 * 4 + 3) * 265 + so] = v.w;
    }
    for (int i = t; i < K2_WS / 4; i += 256)
        ((float4*)ws)[i] = ((const float4*)w2)[i];
    if (t < 54) bss[t] = bases[t];
    __syncthreads();

    const int p  = t & 63;
    const int g  = t >> 6;
    const int co = g * 9;
    float acc0[9] = {}, acc1[9] = {};

    for (int kw = 0; kw < 3; kw++) {
        for (int ci = 0; ci < CMID; ci++) {
            float a[4];
            #pragma unroll
            for (int r = 0; r < 4; r++) a[r] = slab[ci * 265 + r * 66 + p + kw];
            #pragma unroll
            for (int kh = 0; kh < 3; kh++) {
                const float* wrow = ws + ((kh * 3 + kw) * CMID + ci) * BSZ + co;
                #pragma unroll
                for (int j = 0; j < 9; j++) {
                    float wv = wrow[j];
                    acc0[j] = fmaf(a[kh],     wv, acc0[j]);
                    acc1[j] = fmaf(a[kh + 1], wv, acc1[j]);
                }
            }
        }
    }

    const float invs = rsqrtf(1.0f + 1e-3f);
    const float gs0 = gamma2[h0] * invs,     bb0 = beta2[h0];
    const float gs1 = gamma2[h0 + 1] * invs, bb1 = beta2[h0 + 1];
    #pragma unroll
    for (int j = 0; j < 9; j++) {
        float bj = b2[co + j];
        bfs[(0 * 64 + p) * 37 + co + j] = fmaxf(fmaf(acc0[j] + bj, gs0, bb0), 0.f);
        bfs[(1 * 64 + p) * 37 + co + j] = fmaxf(fmaf(acc1[j] + bj, gs1, bb1), 0.f);
    }
    __syncthreads();

    const int pp = t >> 1;
    const int half = t & 1;
    const float* bf = bfs + pp * 37;
    const int rr = pp >> 6, pw = pp & 63;
    float* outp = g_dyn + (size_t)((((nb << 6) + h0 + rr) << 6) + pw) * 54;
    #pragma unroll
    for (int q = 0; q < 27; q++) {
        int idx = half * 27 + q;
        int m = idx / 9, l = idx % 9;
        float s = 0.f;
        #pragma unroll
        for (int k = 0; k < 6; k++) s = fmaf(bf[m * 6 + k], bss[k * 9 + l], s);
        outp[idx] = s;
    }
}

// ===========================================================================
// Kernel 3a: bases_out A -> g_A[65536][768] (tf32-rounded)
// grid = 1024 (1 image row), block 256. slab only: [ci][3*66] stride 199
// (102KB -> 2 CTAs/SM). dyn read warp-uniform from gmem. Lane covers
// channels {lane, lane+32, lane+64, lane+96} (conflict-free slab reads).
// ===========================================================================
#define K3A_SSTR 199
#define K3A_SMEM (CIN * K3A_SSTR * 4)     // 101888 B

__global__ __launch_bounds__(256, 2)
void k3a_kernel(const float* __restrict__ x) {
    extern __shared__ float sm[];
    float* slab = sm;

    const int t  = threadIdx.x;
    const int bx = blockIdx.x;
    const int nb = bx >> 6;
    const int h  = bx & 63;

    // x slab: rows h-1..h+1 (3), cols -1..64 (66), 128 ci, transposed
    const float4* x4 = (const float4*)x;
    for (int idx = t; idx < 3 * 66 * 32; idx += 256) {
        int ci4 = idx & 31;
        int col = (idx >> 5) % 66;
        int r   = idx / (32 * 66);
        int hh  = h + r - 1, ww = col - 1;
        float4 v = make_float4(0.f, 0.f, 0.f, 0.f);
        if (hh >= 0 && hh < HH && ww >= 0 && ww < WW)
            v = x4[((((nb << 6) + hh) << 6) + ww) * 32 + ci4];
        int so = r * 66 + col;
        slab[(ci4 * 4 + 0) * K3A_SSTR + so] = v.x;
        slab[(ci4 * 4 + 1) * K3A_SSTR + so] = v.y;
        slab[(ci4 * 4 + 2) * K3A_SSTR + so] = v.z;
        slab[(ci4 * 4 + 3) * K3A_SSTR + so] = v.w;
    }
    __syncthreads();

    const int w    = t >> 5;
    const int lane = t & 31;

    for (int pp = 0; pp < 8; pp++) {
        const int p = (w << 3) + pp;                 // pixel in row, 0..63
        const size_t pix = (size_t)(bx << 6) + p;
        const float* dp = g_dyn + pix * 54;          // warp-uniform
        float dv[54];
        #pragma unroll
        for (int i = 0; i < 54; i++) dv[i] = __ldg(dp + i);

        float* arow = g_A + pix * 768;
        #pragma unroll
        for (int j = 0; j < 4; j++) {
            const int ch = lane + (j << 5);          // scrambled-channel id
            float pt[9];
            #pragma unroll
            for (int l = 0; l < 9; l++) {
                const int f  = ch * 9 + l;
                const int cc = f & 127;
                const int pi = f >> 7;
                pt[l] = slab[cc * K3A_SSTR + (pi / 3) * 66 + (pi % 3) + p];
            }
            uint32_t ov[6];
            #pragma unroll
            for (int m = 0; m < 6; m++) {
                float s = 0.f;
                #pragma unroll
                for (int l = 0; l < 9; l++) s = fmaf(dv[m * 9 + l], pt[l], s);
                ov[m] = tf32_rna(s);
            }
            float2* dst = (float2*)(arow + ch * 6);
            dst[0] = make_float2(__uint_as_float(ov[0]), __uint_as_float(ov[1]));
            dst[1] = make_float2(__uint_as_float(ov[2]), __uint_as_float(ov[3]));
            dst[2] = make_float2(__uint_as_float(ov[4]), __uint_as_float(ov[5]));
        }
    }
}

// ===========================================================================
// Kernel 3b: mma.sync tf32 GEMM out[65536,256] = A x B^T + bias
// grid = 1024 EXACTLY (512 m-tiles x 2 n-tiles).
// ===========================================================================
#define K3B_STR  36
#define K3B_CHNK (128 * K3B_STR)
#define K3B_SMEM (4 * K3B_CHNK * 4)

__global__ __launch_bounds__(256, 1)
void k3b_kernel(const float* __restrict__ bias, float* __restrict__ out) {
    extern __shared__ float sm[];
    float* As[2] = { sm,                sm + K3B_CHNK };
    float* Bs[2] = { sm + 2 * K3B_CHNK, sm + 3 * K3B_CHNK };

    const int t    = threadIdx.x;
    const int bx   = blockIdx.x;
    const int mt   = bx >> 1;
    const int nt   = bx & 1;
    const int wid  = t >> 5;
    const int lane = t & 31;
    const int g    = lane >> 2;
    const int tid4 = lane & 3;

    const float* Abase = g_A  + (size_t)(mt << 7) * 768;
    const float* Bbase = g_Bt + (size_t)(nt << 7) * 768;

    for (int i = t; i < 1024; i += 256) {
        int row = i >> 3, seg = i & 7;
        cp_async16(As[0] + row * K3B_STR + seg * 4, Abase + row * 768 + seg * 4);
        cp_async16(Bs[0] + row * K3B_STR + seg * 4, Bbase + row * 768 + seg * 4);
    }
    cp_commit();

    const int wm = wid >> 1, wn = wid & 1;
    const int m0 = wm << 5, n0 = wn << 6;
    float d[2][8][4] = {};

    for (int kc = 0; kc < 24; kc++) {
        cp_wait<0>();
        __syncthreads();
        if (kc < 23) {
            const int nc = kc + 1, buf = nc & 1;
            const float* as = Abase + nc * 32;
            const float* bs = Bbase + nc * 32;
            for (int i = t; i < 1024; i += 256) {
                int row = i >> 3, seg = i & 7;
                cp_async16(As[buf] + row * K3B_STR + seg * 4, as + row * 768 + seg * 4);
                cp_async16(Bs[buf] + row * K3B_STR + seg * 4, bs + row * 768 + seg * 4);
            }
            cp_commit();
        }
        const float* Ac = As[kc & 1];
        const float* Bc = Bs[kc & 1];

        #pragma unroll
        for (int kt = 0; kt < 4; kt++) {
            const int k0 = kt << 3;
            uint32_t a[2][4], b[8][2];
            #pragma unroll
            for (int mi = 0; mi < 2; mi++) {
                const float* ap = Ac + (m0 + (mi << 4) + g) * K3B_STR + k0 + tid4;
                a[mi][0] = __float_as_uint(ap[0]);
                a[mi][1] = __float_as_uint(ap[8 * K3B_STR]);
                a[mi][2] = __float_as_uint(ap[4]);
                a[mi][3] = __float_as_uint(ap[8 * K3B_STR + 4]);
            }
            #pragma unroll
            for (int ni = 0; ni < 8; ni++) {
                const float* bp = Bc + (n0 + (ni << 3) + g) * K3B_STR + k0 + tid4;
                b[ni][0] = __float_as_uint(bp[0]);
                b[ni][1] = __float_as_uint(bp[4]);
            }
            #pragma unroll
            for (int mi = 0; mi < 2; mi++)
                #pragma unroll
                for (int ni = 0; ni < 8; ni++)
                    mma_tf32(d[mi][ni], a[mi], b[ni]);
        }
        __syncthreads();
    }

    const size_t rbase = (size_t)(mt << 7) + m0;
    const int    cbase = (nt << 7) + n0 + (tid4 << 1);
    #pragma unroll
    for (int mi = 0; mi < 2; mi++) {
        float* r0 = out + (rbase + (mi << 4) + g) * OO;
        float* r1 = r0 + 8 * OO;
        #pragma unroll
        for (int ni = 0; ni < 8; ni++) {
            const int c = cbase + (ni << 3);
            const float b0 = bias[c], b1 = bias[c + 1];
            *(float2*)(r0 + c) = make_float2(d[mi][ni][0] + b0, d[mi][ni][1] + b1);
            *(float2*)(r1 + c) = make_float2(d[mi][ni][2] + b0, d[mi][ni][3] + b1);
        }
    }
}

// ===========================================================================
extern "C" void kernel_launch(void* const* d_in, const int* in_sizes, int n_in,
                              void* d_out, int out_size) {
    const float* x      = (const float*)d_in[0];
    const float* w1     = (const float*)d_in[1];
    const float* b1     = (const float*)d_in[2];
    const float* gamma1 = (const float*)d_in[3];
    const float* beta1  = (const float*)d_in[4];
    const float* w2     = (const float*)d_in[5];
    const float* b2     = (const float*)d_in[6];
    const float* gamma2 = (const float*)d_in[7];
    const float* beta2  = (const float*)d_in[8];
    const float* bases  = (const float*)d_in[9];
    const float* coef   = (const float*)d_in[10];
    const float* bias   = (const float*)d_in[11];
    float* out = (float*)d_out;

    cudaFuncSetAttribute(conv1_kernel, cudaFuncAttributeMaxDynamicSharedMemorySize, C1_SMEM);
    cudaFuncSetAttribute(conv2_kernel, cudaFuncAttributeMaxDynamicSharedMemorySize, K2_SMEM);
    cudaFuncSetAttribute(k3a_kernel,   cudaFuncAttributeMaxDynamicSharedMemorySize, K3A_SMEM);
    cudaFuncSetAttribute(k3b_kernel,   cudaFuncAttributeMaxDynamicSharedMemorySize, K3B_SMEM);

    prepW_kernel<<<576, 128>>>(w1);
    prepB_kernel<<<OO,  256>>>(coef);
    conv1_kernel<<<NB * HH,     256, C1_SMEM>>>(x, b1, gamma1, beta1);
    conv2_kernel<<<NB * HH / 2, 256, K2_SMEM>>>(w2, b2, gamma2, beta2, bases);
    k3a_kernel  <<<NB * HH,     256, K3A_SMEM>>>(x);
    k3b_kernel  <<<1024,        256, K3B_SMEM>>>(bias, out);
}

// round 8
// speedup vs baseline: 2.9369x; 1.1732x over previous
#include <cuda_runtime.h>
#include <cuda_bf16.h>
#include <cstdint>

// ---------------------------------------------------------------------------
// Conv_DCFD on sm_100 (no tcgen05 in this toolchain): conv1, conv2 and the
// final 1x1 GEMM all run on the tensor pipe via mma.sync tf32 (rna-rounded).
// Shapes: N=16,H=64,W=64,C=128, inter=64, bases=36, M=6, O=256
// ---------------------------------------------------------------------------

#define NB   16
#define HH   64
#define WW   64
#define CIN  128
#define CMID 64
#define BSZ  36
#define OO   256

// scratch (no cudaMalloc allowed)
__device__ float g_h   [NB * HH * WW * CMID];     // 16.8 MB
__device__ float g_dyn [NB * HH * WW * 54];       // 14.2 MB
__device__ float g_A   [NB * HH * WW * 768];      // 201 MB (tf32-rounded)
__device__ float g_Bt  [OO * 768];                // 768 KB (B^T, tf32-rounded)
__device__ float g_W1t [9 * CMID * CIN];          // w1^T per tap, tf32
__device__ float g_W2t [48 * 576];                // w2^T co-major (pad 36->48), tf32

__device__ __forceinline__ void cp_async16(void* smem_dst, const void* gmem_src) {
    unsigned s = (unsigned)__cvta_generic_to_shared(smem_dst);
    asm volatile("cp.async.cg.shared.global [%0], [%1], 16;\n" :: "r"(s), "l"(gmem_src));
}
__device__ __forceinline__ void cp_commit() { asm volatile("cp.async.commit_group;\n"); }
template<int N> __device__ __forceinline__ void cp_wait() {
    asm volatile("cp.async.wait_group %0;\n" :: "n"(N));
}
__device__ __forceinline__ uint32_t tf32_rna(float v) {
    uint32_t r;
    asm("cvt.rna.tf32.f32 %0, %1;" : "=r"(r) : "f"(v));
    return r;
}
__device__ __forceinline__ void mma_tf32(float* d, const uint32_t* a, const uint32_t* b) {
    asm volatile(
        "mma.sync.aligned.m16n8k8.row.col.f32.tf32.tf32.f32 "
        "{%0,%1,%2,%3}, {%4,%5,%6,%7}, {%8,%9}, {%0,%1,%2,%3};"
        : "+f"(d[0]), "+f"(d[1]), "+f"(d[2]), "+f"(d[3])
        : "r"(a[0]), "r"(a[1]), "r"(a[2]), "r"(a[3]), "r"(b[0]), "r"(b[1]));
}

// ===========================================================================
// prep kernels: transpose + tf32-round weights
// ===========================================================================
__global__ void prepW_kernel(const float* __restrict__ w1) {
    const int bx = blockIdx.x;          // kk*64+co (576)
    const int t  = threadIdx.x;         // ci (128)
    const int kk = bx >> 6, co = bx & 63;
    g_W1t[bx * 128 + t] = __uint_as_float(tf32_rna(w1[(kk * 128 + t) * 64 + co]));
}

__global__ void prepW2_kernel(const float* __restrict__ w2) {
    const int n = blockIdx.x;           // 0..47 (co, padded)
    const int k = threadIdx.x;          // 0..575 (kk*64+ci)
    float v = 0.f;
    if (n < BSZ) {
        const int kk = k >> 6, ci = k & 63;
        v = w2[(kk * 64 + ci) * BSZ + n];
    }
    g_W2t[n * 576 + k] = __uint_as_float(tf32_rna(v));
}

__global__ void prepB_kernel(const float* __restrict__ coef) {
    const int n = blockIdx.x;
    const int t = threadIdx.x;
    #pragma unroll
    for (int q = 0; q < 3; q++) {
        int k = q * 256 + t;
        g_Bt[n * 768 + k] = __uint_as_float(tf32_rna(coef[k * OO + n]));
    }
}

// ===========================================================================
// Kernel 1: conv1 via mma.sync tf32 + BN(axis=H) + ReLU -> g_h  (passing)
// ===========================================================================
#define C1_SSTR  132
#define C1_SLAB  (198 * C1_SSTR)
#define C1_WSTR  140
#define C1_WCH   (CMID * C1_WSTR)
#define C1_SMEM  ((C1_SLAB + 2 * C1_WCH) * 4)

__global__ __launch_bounds__(256, 1)
void conv1_kernel(const float* __restrict__ x, const float* __restrict__ b1,
                  const float* __restrict__ gamma1, const float* __restrict__ beta1) {
    extern __shared__ float sm[];
    float* slab = sm;
    float* wbuf = sm + C1_SLAB;

    const int t  = threadIdx.x;
    const int bx = blockIdx.x;
    const int nb = bx >> 6;
    const int h  = bx & 63;

    for (int i = t; i < 2048; i += 256) {
        int row = i >> 5, seg = i & 31;
        cp_async16(wbuf + row * C1_WSTR + seg * 4, g_W1t + row * 128 + seg * 4);
    }
    cp_commit();

    const float4* x4 = (const float4*)x;
    for (int idx = t; idx < 3 * 66 * 32; idx += 256) {
        int ci4 = idx & 31;
        int col = (idx >> 5) % 66;
        int r   = idx / (32 * 66);
        int hh  = h + r - 1, ww = col - 1;
        float4 v = make_float4(0.f, 0.f, 0.f, 0.f);
        if (hh >= 0 && hh < HH && ww >= 0 && ww < WW)
            v = x4[((((nb << 6) + hh) << 6) + ww) * 32 + ci4];
        float4 o;
        o.x = __uint_as_float(tf32_rna(v.x));
        o.y = __uint_as_float(tf32_rna(v.y));
        o.z = __uint_as_float(tf32_rna(v.z));
        o.w = __uint_as_float(tf32_rna(v.w));
        *(float4*)(slab + (r * 66 + col) * C1_SSTR + ci4 * 4) = o;
    }
    cp_wait<0>();
    __syncthreads();

    const int wid  = t >> 5;
    const int lane = t & 31;
    const int g    = lane >> 2;
    const int t4   = lane & 3;
    const int wm   = wid >> 2;
    const int wn   = wid & 3;
    const int prow = wm << 5;

    float d[2][2][4] = {};

    for (int kk = 0; kk < 9; kk++) {
        const float* wb = wbuf + (kk & 1) * C1_WCH;
        if (kk < 8) {
            float* dst = wbuf + ((kk + 1) & 1) * C1_WCH;
            const float* src = g_W1t + (kk + 1) * 8192;
            for (int i = t; i < 2048; i += 256) {
                int row = i >> 5, seg = i & 31;
                cp_async16(dst + row * C1_WSTR + seg * 4, src + row * 128 + seg * 4);
            }
            cp_commit();
        }
        const int kh = kk / 3, kw = kk % 3;
        const float* arow = slab + (kh * 66 + kw + prow + g) * C1_SSTR;

        #pragma unroll
        for (int kt = 0; kt < 16; kt++) {
            const int k0 = kt << 3;
            uint32_t a[2][4], b[2][2];
            #pragma unroll
            for (int mi = 0; mi < 2; mi++) {
                const float* ap = arow + (mi << 4) * C1_SSTR + k0 + t4;
                a[mi][0] = __float_as_uint(ap[0]);
                a[mi][1] = __float_as_uint(ap[8 * C1_SSTR]);
                a[mi][2] = __float_as_uint(ap[4]);
                a[mi][3] = __float_as_uint(ap[8 * C1_SSTR + 4]);
            }
            #pragma unroll
            for (int ni = 0; ni < 2; ni++) {
                const float* bp = wb + ((wn << 4) + (ni << 3) + g) * C1_WSTR + k0 + t4;
                b[ni][0] = __float_as_uint(bp[0]);
                b[ni][1] = __float_as_uint(bp[4]);
            }
            #pragma unroll
            for (int mi = 0; mi < 2; mi++)
                #pragma unroll
                for (int ni = 0; ni < 2; ni++)
                    mma_tf32(d[mi][ni], a[mi], b[ni]);
        }
        cp_wait<0>();
        __syncthreads();
    }

    const float invs = rsqrtf(1.0f + 1e-3f);
    const float gs = gamma1[h] * invs;
    const float bb = beta1[h];
    #pragma unroll
    for (int mi = 0; mi < 2; mi++) {
        const int p0 = prow + (mi << 4) + g;
        float* r0 = g_h + ((size_t)(bx << 6) + p0) * CMID;
        float* r1 = r0 + 8 * CMID;
        #pragma unroll
        for (int ni = 0; ni < 2; ni++) {
            const int c = (wn << 4) + (ni << 3) + (t4 << 1);
            const float bc0 = b1[c], bc1 = b1[c + 1];
            float2 v0, v1;
            v0.x = fmaxf(fmaf(d[mi][ni][0] + bc0, gs, bb), 0.f);
            v0.y = fmaxf(fmaf(d[mi][ni][1] + bc1, gs, bb), 0.f);
            v1.x = fmaxf(fmaf(d[mi][ni][2] + bc0, gs, bb), 0.f);
            v1.y = fmaxf(fmaf(d[mi][ni][3] + bc1, gs, bb), 0.f);
            *(float2*)(r0 + c) = v0;
            *(float2*)(r1 + c) = v1;
        }
    }
}

// ===========================================================================
// Kernel 2: conv2 via mma.sync tf32 + BN + ReLU + xFB -> g_dyn
// grid = 512 (nb, h0 = 2 rows = 128 px), block 256 (8 warps, 4m x 2n).
// Block tile 128px x 48co (co>=36 discarded), K=576 (9 taps x 64 ci).
// slab: g_h rows h0-1..h0+2, [row66][ci] stride 68; w2s [48][576] stride 580.
// Epilogue: bfeat -> smem (overlay w2s) -> xFB dyn stage.
// ===========================================================================
#define C2_SSTR  68
#define C2_SLAB  (264 * C2_SSTR)        // 17952 floats
#define C2_WSTR  580
#define C2_WS    (48 * C2_WSTR)         // 27840 floats
#define C2_SMEM  ((C2_SLAB + C2_WS + 64) * 4)   // 183424 B

__global__ __launch_bounds__(256, 1)
void conv2_kernel(const float* __restrict__ b2, const float* __restrict__ gamma2,
                  const float* __restrict__ beta2, const float* __restrict__ bases) {
    extern __shared__ float sm[];
    float* slab = sm;
    float* ws   = sm + C2_SLAB;
    float* bss  = sm + C2_SLAB + C2_WS;

    const int t  = threadIdx.x;
    const int bx = blockIdx.x;
    const int nb = bx >> 5;
    const int h0 = (bx & 31) << 1;

    // w2s: 48 rows x 144 float4 segs
    for (int i = t; i < 6912; i += 256) {
        int row = i / 144, seg = i % 144;
        cp_async16(ws + row * C2_WSTR + seg * 4, g_W2t + row * 576 + seg * 4);
    }
    cp_commit();
    if (t < 54) bss[t] = bases[t];

    // slab: g_h rows h0-1..h0+2 (4), cols -1..64 (66), 64 ci (direct, no transpose)
    const float4* h4 = (const float4*)g_h;
    for (int idx = t; idx < 4 * 66 * 16; idx += 256) {
        int seg = idx & 15;
        int pos = idx >> 4;
        int r   = pos / 66, col = pos % 66;
        int hh  = h0 + r - 1, ww = col - 1;
        float4 v = make_float4(0.f, 0.f, 0.f, 0.f);
        if (hh >= 0 && hh < HH && ww >= 0 && ww < WW)
            v = h4[(size_t)((((nb << 6) + hh) << 6) + ww) * 16 + seg];
        *(float4*)(slab + (r * 66 + col) * C2_SSTR + seg * 4) = v;
    }
    cp_wait<0>();
    __syncthreads();

    const int wid  = t >> 5;
    const int lane = t & 31;
    const int g    = lane >> 2;
    const int t4   = lane & 3;
    const int wm   = wid >> 1;          // 0..3 (32-px group)
    const int wn   = wid & 1;           // 0..1 (24-co group)
    const int p0   = wm << 5;           // pixel base
    const int r    = p0 >> 6;           // image row within pair
    const int wcol = p0 & 63;

    float d[2][3][4] = {};

    #pragma unroll
    for (int kk = 0; kk < 9; kk++) {
        const int kh = kk / 3, kw = kk % 3;
        const float* arow = slab + ((r + kh) * 66 + kw + wcol + g) * C2_SSTR;
        const float* brow = ws + (wn * 24 + g) * C2_WSTR + kk * 64;
        #pragma unroll
        for (int kt = 0; kt < 8; kt++) {
            const int k0 = kt << 3;
            uint32_t a[2][4], b[3][2];
            #pragma unroll
            for (int mi = 0; mi < 2; mi++) {
                const float* ap = arow + (mi << 4) * C2_SSTR + k0 + t4;
                a[mi][0] = __float_as_uint(ap[0]);
                a[mi][1] = __float_as_uint(ap[8 * C2_SSTR]);
                a[mi][2] = __float_as_uint(ap[4]);
                a[mi][3] = __float_as_uint(ap[8 * C2_SSTR + 4]);
            }
            #pragma unroll
            for (int ni = 0; ni < 3; ni++) {
                const float* bp = brow + (ni << 3) * C2_WSTR + k0 + t4;
                b[ni][0] = __float_as_uint(bp[0]);
                b[ni][1] = __float_as_uint(bp[4]);
            }
            #pragma unroll
            for (int mi = 0; mi < 2; mi++)
                #pragma unroll
                for (int ni = 0; ni < 3; ni++)
                    mma_tf32(d[mi][ni], a[mi], b[ni]);
        }
    }
    __syncthreads();

    // bfeat (BN+ReLU) -> bfs overlay on ws
    float* bfs = ws;                     // [128][37]
    const float invs = rsqrtf(1.0f + 1e-3f);
    const float gs = gamma2[h0 + r] * invs;
    const float bb = beta2[h0 + r];
    #pragma unroll
    for (int mi = 0; mi < 2; mi++) {
        const int p = p0 + (mi << 4) + g;
        #pragma unroll
        for (int ni = 0; ni < 3; ni++) {
            const int c = wn * 24 + (ni << 3) + (t4 << 1);
            if (c < BSZ) {
                const float bj0 = b2[c], bj1 = b2[c + 1];
                bfs[p * 37 + c]           = fmaxf(fmaf(d[mi][ni][0] + bj0, gs, bb), 0.f);
                bfs[p * 37 + c + 1]       = fmaxf(fmaf(d[mi][ni][1] + bj1, gs, bb), 0.f);
                bfs[(p + 8) * 37 + c]     = fmaxf(fmaf(d[mi][ni][2] + bj0, gs, bb), 0.f);
                bfs[(p + 8) * 37 + c + 1] = fmaxf(fmaf(d[mi][ni][3] + bj1, gs, bb), 0.f);
            }
        }
    }
    __syncthreads();

    // dyn[m][l] = sum_k bfeat[m*6+k] * bases[k][l]
    const int pp = t >> 1;
    const int half = t & 1;
    const float* bf = bfs + pp * 37;
    const int rr = pp >> 6, pw = pp & 63;
    float* outp = g_dyn + (size_t)((((nb << 6) + h0 + rr) << 6) + pw) * 54;
    #pragma unroll
    for (int q = 0; q < 27; q++) {
        int idx = half * 27 + q;
        int m = idx / 9, l = idx % 9;
        float s = 0.f;
        #pragma unroll
        for (int k = 0; k < 6; k++) s = fmaf(bf[m * 6 + k], bss[k * 9 + l], s);
        outp[idx] = s;
    }
}

// ===========================================================================
// Kernel 3a: bases_out A -> g_A[65536][768] (tf32-rounded)  (passing)
// ===========================================================================
#define K3A_SSTR 199
#define K3A_SMEM (CIN * K3A_SSTR * 4)

__global__ __launch_bounds__(256, 2)
void k3a_kernel(const float* __restrict__ x) {
    extern __shared__ float sm[];
    float* slab = sm;

    const int t  = threadIdx.x;
    const int bx = blockIdx.x;
    const int nb = bx >> 6;
    const int h  = bx & 63;

    const float4* x4 = (const float4*)x;
    for (int idx = t; idx < 3 * 66 * 32; idx += 256) {
        int ci4 = idx & 31;
        int col = (idx >> 5) % 66;
        int r   = idx / (32 * 66);
        int hh  = h + r - 1, ww = col - 1;
        float4 v = make_float4(0.f, 0.f, 0.f, 0.f);
        if (hh >= 0 && hh < HH && ww >= 0 && ww < WW)
            v = x4[((((nb << 6) + hh) << 6) + ww) * 32 + ci4];
        int so = r * 66 + col;
        slab[(ci4 * 4 + 0) * K3A_SSTR + so] = v.x;
        slab[(ci4 * 4 + 1) * K3A_SSTR + so] = v.y;
        slab[(ci4 * 4 + 2) * K3A_SSTR + so] = v.z;
        slab[(ci4 * 4 + 3) * K3A_SSTR + so] = v.w;
    }
    __syncthreads();

    const int w    = t >> 5;
    const int lane = t & 31;

    for (int pp = 0; pp < 8; pp++) {
        const int p = (w << 3) + pp;
        const size_t pix = (size_t)(bx << 6) + p;
        const float* dp = g_dyn + pix * 54;
        float dv[54];
        #pragma unroll
        for (int i = 0; i < 54; i++) dv[i] = __ldg(dp + i);

        float* arow = g_A + pix * 768;
        #pragma unroll
        for (int j = 0; j < 4; j++) {
            const int ch = lane + (j << 5);
            float pt[9];
            #pragma unroll
            for (int l = 0; l < 9; l++) {
                const int f  = ch * 9 + l;
                const int cc = f & 127;
                const int pi = f >> 7;
                pt[l] = slab[cc * K3A_SSTR + (pi / 3) * 66 + (pi % 3) + p];
            }
            uint32_t ov[6];
            #pragma unroll
            for (int m = 0; m < 6; m++) {
                float s = 0.f;
                #pragma unroll
                for (int l = 0; l < 9; l++) s = fmaf(dv[m * 9 + l], pt[l], s);
                ov[m] = tf32_rna(s);
            }
            float2* dst = (float2*)(arow + ch * 6);
            dst[0] = make_float2(__uint_as_float(ov[0]), __uint_as_float(ov[1]));
            dst[1] = make_float2(__uint_as_float(ov[2]), __uint_as_float(ov[3]));
            dst[2] = make_float2(__uint_as_float(ov[4]), __uint_as_float(ov[5]));
        }
    }
}

// ===========================================================================
// Kernel 3b: mma.sync tf32 GEMM out[65536,256] = A x B^T + bias
// grid = 512 (mt), block 512 (16 warps, 4m x 4n) -> block tile 128x256:
// A is read ONCE (was twice with the 128x128 tiling).
// ===========================================================================
#define K3B_STR  36
#define K3B_ACH  (128 * K3B_STR)         // 4608 floats
#define K3B_BCH  (256 * K3B_STR)         // 9216 floats
#define K3B_SMEM ((2 * K3B_ACH + 2 * K3B_BCH) * 4)   // 110592 B

__global__ __launch_bounds__(512, 1)
void k3b_kernel(const float* __restrict__ bias, float* __restrict__ out) {
    extern __shared__ float sm[];
    float* As[2] = { sm,              sm + K3B_ACH };
    float* Bs[2] = { sm + 2 * K3B_ACH, sm + 2 * K3B_ACH + K3B_BCH };

    const int t    = threadIdx.x;
    const int mt   = blockIdx.x;
    const int wid  = t >> 5;
    const int lane = t & 31;
    const int g    = lane >> 2;
    const int tid4 = lane & 3;

    const float* Abase = g_A + (size_t)(mt << 7) * 768;

    for (int i = t; i < 1024; i += 512) {
        int row = i >> 3, seg = i & 7;
        cp_async16(As[0] + row * K3B_STR + seg * 4, Abase + row * 768 + seg * 4);
    }
    for (int i = t; i < 2048; i += 512) {
        int row = i >> 3, seg = i & 7;
        cp_async16(Bs[0] + row * K3B_STR + seg * 4, g_Bt + row * 768 + seg * 4);
    }
    cp_commit();

    const int wm = wid >> 2, wn = wid & 3;
    const int m0 = wm << 5, n0 = wn << 6;
    float d[2][8][4] = {};

    for (int kc = 0; kc < 24; kc++) {
        cp_wait<0>();
        __syncthreads();
        if (kc < 23) {
            const int nc = kc + 1, buf = nc & 1;
            const float* as = Abase + nc * 32;
            const float* bs = g_Bt + nc * 32;
            for (int i = t; i < 1024; i += 512) {
                int row = i >> 3, seg = i & 7;
                cp_async16(As[buf] + row * K3B_STR + seg * 4, as + row * 768 + seg * 4);
            }
            for (int i = t; i < 2048; i += 512) {
                int row = i >> 3, seg = i & 7;
                cp_async16(Bs[buf] + row * K3B_STR + seg * 4, bs + row * 768 + seg * 4);
            }
            cp_commit();
        }
        const float* Ac = As[kc & 1];
        const float* Bc = Bs[kc & 1];

        #pragma unroll
        for (int kt = 0; kt < 4; kt++) {
            const int k0 = kt << 3;
            uint32_t a[2][4], b[8][2];
            #pragma unroll
            for (int mi = 0; mi < 2; mi++) {
                const float* ap = Ac + (m0 + (mi << 4) + g) * K3B_STR + k0 + tid4;
                a[mi][0] = __float_as_uint(ap[0]);
                a[mi][1] = __float_as_uint(ap[8 * K3B_STR]);
                a[mi][2] = __float_as_uint(ap[4]);
                a[mi][3] = __float_as_uint(ap[8 * K3B_STR + 4]);
            }
            #pragma unroll
            for (int ni = 0; ni < 8; ni++) {
                const float* bp = Bc + (n0 + (ni << 3) + g) * K3B_STR + k0 + tid4;
                b[ni][0] = __float_as_uint(bp[0]);
                b[ni][1] = __float_as_uint(bp[4]);
            }
            #pragma unroll
            for (int mi = 0; mi < 2; mi++)
                #pragma unroll
                for (int ni = 0; ni < 8; ni++)
                    mma_tf32(d[mi][ni], a[mi], b[ni]);
        }
        __syncthreads();
    }

    const size_t rbase = (size_t)(mt << 7) + m0;
    const int    cbase = n0 + (tid4 << 1);
    #pragma unroll
    for (int mi = 0; mi < 2; mi++) {
        float* r0 = out + (rbase + (mi << 4) + g) * OO;
        float* r1 = r0 + 8 * OO;
        #pragma unroll
        for (int ni = 0; ni < 8; ni++) {
            const int c = cbase + (ni << 3);
            const float b0 = bias[c], b1 = bias[c + 1];
            *(float2*)(r0 + c) = make_float2(d[mi][ni][0] + b0, d[mi][ni][1] + b1);
            *(float2*)(r1 + c) = make_float2(d[mi][ni][2] + b0, d[mi][ni][3] + b1);
        }
    }
}

// ===========================================================================
extern "C" void kernel_launch(void* const* d_in, const int* in_sizes, int n_in,
                              void* d_out, int out_size) {
    const float* x      = (const float*)d_in[0];
    const float* w1     = (const float*)d_in[1];
    const float* b1     = (const float*)d_in[2];
    const float* gamma1 = (const float*)d_in[3];
    const float* beta1  = (const float*)d_in[4];
    const float* w2     = (const float*)d_in[5];
    const float* b2     = (const float*)d_in[6];
    const float* gamma2 = (const float*)d_in[7];
    const float* beta2  = (const float*)d_in[8];
    const float* bases  = (const float*)d_in[9];
    const float* coef   = (const float*)d_in[10];
    const float* bias   = (const float*)d_in[11];
    float* out = (float*)d_out;

    cudaFuncSetAttribute(conv1_kernel, cudaFuncAttributeMaxDynamicSharedMemorySize, C1_SMEM);
    cudaFuncSetAttribute(conv2_kernel, cudaFuncAttributeMaxDynamicSharedMemorySize, C2_SMEM);
    cudaFuncSetAttribute(k3a_kernel,   cudaFuncAttributeMaxDynamicSharedMemorySize, K3A_SMEM);
    cudaFuncSetAttribute(k3b_kernel,   cudaFuncAttributeMaxDynamicSharedMemorySize, K3B_SMEM);

    prepW_kernel <<<576, 128>>>(w1);
    prepW2_kernel<<<48,  576>>>(w2);
    prepB_kernel <<<OO,  256>>>(coef);
    conv1_kernel<<<NB * HH,     256, C1_SMEM>>>(x, b1, gamma1, beta1);
    conv2_kernel<<<NB * HH / 2, 256, C2_SMEM>>>(b2, gamma2, beta2, bases);
    k3a_kernel  <<<NB * HH,     256, K3A_SMEM>>>(x);
    k3b_kernel  <<<512,         512, K3B_SMEM>>>(bias, out);
}

// round 9
// speedup vs baseline: 3.0446x; 1.0367x over previous
#include <cuda_runtime.h>
#include <cuda_bf16.h>
#include <cstdint>

// ---------------------------------------------------------------------------
// Conv_DCFD on sm_100 (no tcgen05 in this toolchain): conv1, conv2 and the
// final 1x1 GEMM all run on the tensor pipe via mma.sync tf32 (rna-rounded).
// Shapes: N=16,H=64,W=64,C=128, inter=64, bases=36, M=6, O=256
// ---------------------------------------------------------------------------

#define NB   16
#define HH   64
#define WW   64
#define CIN  128
#define CMID 64
#define BSZ  36
#define OO   256

// scratch (no cudaMalloc allowed)
__device__ float g_h   [NB * HH * WW * CMID];     // 16.8 MB
__device__ float g_dyn [NB * HH * WW * 54];       // 14.2 MB
__device__ float g_A   [NB * HH * WW * 768];      // 201 MB (tf32-rounded)
__device__ float g_Bt  [OO * 768];                // 768 KB (B^T, tf32-rounded)
__device__ float g_W1t [9 * CMID * CIN];          // w1^T per tap, tf32
__device__ float g_W2t [48 * 576];                // w2^T co-major (pad 36->48), tf32

__device__ __forceinline__ void cp_async16(void* smem_dst, const void* gmem_src) {
    unsigned s = (unsigned)__cvta_generic_to_shared(smem_dst);
    asm volatile("cp.async.cg.shared.global [%0], [%1], 16;\n" :: "r"(s), "l"(gmem_src));
}
__device__ __forceinline__ void cp_commit() { asm volatile("cp.async.commit_group;\n"); }
template<int N> __device__ __forceinline__ void cp_wait() {
    asm volatile("cp.async.wait_group %0;\n" :: "n"(N));
}
__device__ __forceinline__ uint32_t tf32_rna(float v) {
    uint32_t r;
    asm("cvt.rna.tf32.f32 %0, %1;" : "=r"(r) : "f"(v));
    return r;
}
__device__ __forceinline__ void mma_tf32(float* d, const uint32_t* a, const uint32_t* b) {
    asm volatile(
        "mma.sync.aligned.m16n8k8.row.col.f32.tf32.tf32.f32 "
        "{%0,%1,%2,%3}, {%4,%5,%6,%7}, {%8,%9}, {%0,%1,%2,%3};"
        : "+f"(d[0]), "+f"(d[1]), "+f"(d[2]), "+f"(d[3])
        : "r"(a[0]), "r"(a[1]), "r"(a[2]), "r"(a[3]), "r"(b[0]), "r"(b[1]));
}

// ===========================================================================
// prep kernels: transpose + tf32-round weights
// ===========================================================================
__global__ void prepW_kernel(const float* __restrict__ w1) {
    const int bx = blockIdx.x;          // kk*64+co (576)
    const int t  = threadIdx.x;         // ci (128)
    const int kk = bx >> 6, co = bx & 63;
    g_W1t[bx * 128 + t] = __uint_as_float(tf32_rna(w1[(kk * 128 + t) * 64 + co]));
}

__global__ void prepW2_kernel(const float* __restrict__ w2) {
    const int n = blockIdx.x;           // 0..47 (co, padded)
    const int k = threadIdx.x;          // 0..575 (kk*64+ci)
    float v = 0.f;
    if (n < BSZ) {
        const int kk = k >> 6, ci = k & 63;
        v = w2[(kk * 64 + ci) * BSZ + n];
    }
    g_W2t[n * 576 + k] = __uint_as_float(tf32_rna(v));
}

__global__ void prepB_kernel(const float* __restrict__ coef) {
    const int n = blockIdx.x;
    const int t = threadIdx.x;
    #pragma unroll
    for (int q = 0; q < 3; q++) {
        int k = q * 256 + t;
        g_Bt[n * 768 + k] = __uint_as_float(tf32_rna(coef[k * OO + n]));
    }
}

// ===========================================================================
// Kernel 1: conv1 via mma.sync tf32 + BN(axis=H) + ReLU -> g_h
// grid = 512 (nb, h0 = 2 rows = 128 px), block 512 (16 warps, 4m x 4n),
// warp tile 32px x 16co. slab: x rows h0-1..h0+2 (4x66), [row66][ci] str 132.
// wbuf [co][ci] stride 140, double-buffered cp.async from g_W1t.
// ===========================================================================
#define C1_SSTR  132
#define C1_SLAB  (264 * C1_SSTR)        // 34848 floats
#define C1_WSTR  140
#define C1_WCH   (CMID * C1_WSTR)       // 8960 floats
#define C1_SMEM  ((C1_SLAB + 2 * C1_WCH) * 4)   // 211072 B

__global__ __launch_bounds__(512, 1)
void conv1_kernel(const float* __restrict__ x, const float* __restrict__ b1,
                  const float* __restrict__ gamma1, const float* __restrict__ beta1) {
    extern __shared__ float sm[];
    float* slab = sm;
    float* wbuf = sm + C1_SLAB;

    const int t  = threadIdx.x;
    const int bx = blockIdx.x;
    const int nb = bx >> 5;
    const int h0 = (bx & 31) << 1;

    // preload weight chunk 0 (64 co rows x 32 float4 segs)
    for (int i = t; i < 2048; i += 512) {
        int row = i >> 5, seg = i & 31;
        cp_async16(wbuf + row * C1_WSTR + seg * 4, g_W1t + row * 128 + seg * 4);
    }
    cp_commit();

    // slab: rows h0-1..h0+2 (4), cols -1..64 (66), 128 ci, tf32-rounded
    const float4* x4 = (const float4*)x;
    for (int idx = t; idx < 4 * 66 * 32; idx += 512) {
        int ci4 = idx & 31;
        int col = (idx >> 5) % 66;
        int r   = idx / (32 * 66);
        int hh  = h0 + r - 1, ww = col - 1;
        float4 v = make_float4(0.f, 0.f, 0.f, 0.f);
        if (hh >= 0 && hh < HH && ww >= 0 && ww < WW)
            v = x4[((((nb << 6) + hh) << 6) + ww) * 32 + ci4];
        float4 o;
        o.x = __uint_as_float(tf32_rna(v.x));
        o.y = __uint_as_float(tf32_rna(v.y));
        o.z = __uint_as_float(tf32_rna(v.z));
        o.w = __uint_as_float(tf32_rna(v.w));
        *(float4*)(slab + (r * 66 + col) * C1_SSTR + ci4 * 4) = o;
    }
    cp_wait<0>();
    __syncthreads();

    const int wid  = t >> 5;
    const int lane = t & 31;
    const int g    = lane >> 2;
    const int t4   = lane & 3;
    const int wm   = wid >> 2;           // 0..3  (32-px group)
    const int wn   = wid & 3;            // 0..3  (16-co group)
    const int p0   = wm << 5;            // pixel base 0..96
    const int r    = p0 >> 6;            // image row within pair (0/1)
    const int col0 = p0 & 63;

    float d[2][2][4] = {};

    for (int kk = 0; kk < 9; kk++) {
        const float* wb = wbuf + (kk & 1) * C1_WCH;
        if (kk < 8) {
            float* dst = wbuf + ((kk + 1) & 1) * C1_WCH;
            const float* src = g_W1t + (kk + 1) * 8192;
            for (int i = t; i < 2048; i += 512) {
                int row = i >> 5, seg = i & 31;
                cp_async16(dst + row * C1_WSTR + seg * 4, src + row * 128 + seg * 4);
            }
            cp_commit();
        }
        const int kh = kk / 3, kw = kk % 3;
        const float* arow = slab + ((r + kh) * 66 + kw + col0 + g) * C1_SSTR;

        #pragma unroll
        for (int kt = 0; kt < 16; kt++) {
            const int k0 = kt << 3;
            uint32_t a[2][4], b[2][2];
            #pragma unroll
            for (int mi = 0; mi < 2; mi++) {
                const float* ap = arow + (mi << 4) * C1_SSTR + k0 + t4;
                a[mi][0] = __float_as_uint(ap[0]);
                a[mi][1] = __float_as_uint(ap[8 * C1_SSTR]);
                a[mi][2] = __float_as_uint(ap[4]);
                a[mi][3] = __float_as_uint(ap[8 * C1_SSTR + 4]);
            }
            #pragma unroll
            for (int ni = 0; ni < 2; ni++) {
                const float* bp = wb + ((wn << 4) + (ni << 3) + g) * C1_WSTR + k0 + t4;
                b[ni][0] = __float_as_uint(bp[0]);
                b[ni][1] = __float_as_uint(bp[4]);
            }
            #pragma unroll
            for (int mi = 0; mi < 2; mi++)
                #pragma unroll
                for (int ni = 0; ni < 2; ni++)
                    mma_tf32(d[mi][ni], a[mi], b[ni]);
        }
        cp_wait<0>();
        __syncthreads();
    }

    const float invs = rsqrtf(1.0f + 1e-3f);
    const float gs = gamma1[h0 + r] * invs;
    const float bb = beta1[h0 + r];
    #pragma unroll
    for (int mi = 0; mi < 2; mi++) {
        const int p = p0 + (mi << 4) + g;
        float* r0 = g_h + ((size_t)(bx << 7) + p) * CMID;
        float* r1 = r0 + 8 * CMID;
        #pragma unroll
        for (int ni = 0; ni < 2; ni++) {
            const int c = (wn << 4) + (ni << 3) + (t4 << 1);
            const float bc0 = b1[c], bc1 = b1[c + 1];
            float2 v0, v1;
            v0.x = fmaxf(fmaf(d[mi][ni][0] + bc0, gs, bb), 0.f);
            v0.y = fmaxf(fmaf(d[mi][ni][1] + bc1, gs, bb), 0.f);
            v1.x = fmaxf(fmaf(d[mi][ni][2] + bc0, gs, bb), 0.f);
            v1.y = fmaxf(fmaf(d[mi][ni][3] + bc1, gs, bb), 0.f);
            *(float2*)(r0 + c) = v0;
            *(float2*)(r1 + c) = v1;
        }
    }
}

// ===========================================================================
// Kernel 2: conv2 via mma.sync tf32 + BN + ReLU + xFB -> g_dyn
// grid = 256 (nb, h0 = 4 rows = 256 px), block 512 (16 warps, 8m x 2n),
// warp tile 32px x 24co. slab: g_h rows h0-1..h0+4 (6x66), [row66][ci] str 68.
// w2s [48][576] stride 580, whole matrix resident. Epilogue overlays ws.
// ===========================================================================
#define C2_SSTR  68
#define C2_SLAB  (396 * C2_SSTR)        // 26928 floats
#define C2_WSTR  580
#define C2_WS    (48 * C2_WSTR)         // 27840 floats
#define C2_SMEM  ((C2_SLAB + C2_WS + 64) * 4)   // 219328 B

__global__ __launch_bounds__(512, 1)
void conv2_kernel(const float* __restrict__ b2, const float* __restrict__ gamma2,
                  const float* __restrict__ beta2, const float* __restrict__ bases) {
    extern __shared__ float sm[];
    float* slab = sm;
    float* ws   = sm + C2_SLAB;
    float* bss  = sm + C2_SLAB + C2_WS;

    const int t  = threadIdx.x;
    const int bx = blockIdx.x;
    const int nb = bx >> 4;
    const int h0 = (bx & 15) << 2;

    // w2s: 48 rows x 144 float4 segs
    for (int i = t; i < 6912; i += 512) {
        int row = i / 144, seg = i % 144;
        cp_async16(ws + row * C2_WSTR + seg * 4, g_W2t + row * 576 + seg * 4);
    }
    cp_commit();
    if (t < 54) bss[t] = bases[t];

    // slab: g_h rows h0-1..h0+4 (6), cols -1..64 (66), 64 ci
    const float4* h4 = (const float4*)g_h;
    for (int idx = t; idx < 6 * 66 * 16; idx += 512) {
        int seg = idx & 15;
        int pos = idx >> 4;
        int r   = pos / 66, col = pos % 66;
        int hh  = h0 + r - 1, ww = col - 1;
        float4 v = make_float4(0.f, 0.f, 0.f, 0.f);
        if (hh >= 0 && hh < HH && ww >= 0 && ww < WW)
            v = h4[(size_t)((((nb << 6) + hh) << 6) + ww) * 16 + seg];
        *(float4*)(slab + (r * 66 + col) * C2_SSTR + seg * 4) = v;
    }
    cp_wait<0>();
    __syncthreads();

    const int wid  = t >> 5;
    const int lane = t & 31;
    const int g    = lane >> 2;
    const int t4   = lane & 3;
    const int wm   = wid >> 1;          // 0..7 (32-px group)
    const int wn   = wid & 1;           // 0..1 (24-co group)
    const int p0   = wm << 5;           // pixel base 0..224
    const int r    = p0 >> 6;           // image row within quad (0..3)
    const int wcol = p0 & 63;

    float d[2][3][4] = {};

    #pragma unroll
    for (int kk = 0; kk < 9; kk++) {
        const int kh = kk / 3, kw = kk % 3;
        const float* arow = slab + ((r + kh) * 66 + kw + wcol + g) * C2_SSTR;
        const float* brow = ws + (wn * 24 + g) * C2_WSTR + kk * 64;
        #pragma unroll
        for (int kt = 0; kt < 8; kt++) {
            const int k0 = kt << 3;
            uint32_t a[2][4], b[3][2];
            #pragma unroll
            for (int mi = 0; mi < 2; mi++) {
                const float* ap = arow + (mi << 4) * C2_SSTR + k0 + t4;
                a[mi][0] = __float_as_uint(ap[0]);
                a[mi][1] = __float_as_uint(ap[8 * C2_SSTR]);
                a[mi][2] = __float_as_uint(ap[4]);
                a[mi][3] = __float_as_uint(ap[8 * C2_SSTR + 4]);
            }
            #pragma unroll
            for (int ni = 0; ni < 3; ni++) {
                const float* bp = brow + (ni << 3) * C2_WSTR + k0 + t4;
                b[ni][0] = __float_as_uint(bp[0]);
                b[ni][1] = __float_as_uint(bp[4]);
            }
            #pragma unroll
            for (int mi = 0; mi < 2; mi++)
                #pragma unroll
                for (int ni = 0; ni < 3; ni++)
                    mma_tf32(d[mi][ni], a[mi], b[ni]);
        }
    }
    __syncthreads();

    // bfeat (BN+ReLU) -> bfs overlay on ws  [256 px][37]
    float* bfs = ws;
    const float invs = rsqrtf(1.0f + 1e-3f);
    const float gs = gamma2[h0 + r] * invs;
    const float bb = beta2[h0 + r];
    #pragma unroll
    for (int mi = 0; mi < 2; mi++) {
        const int p = p0 + (mi << 4) + g;
        #pragma unroll
        for (int ni = 0; ni < 3; ni++) {
            const int c = wn * 24 + (ni << 3) + (t4 << 1);
            if (c < BSZ) {
                const float bj0 = b2[c], bj1 = b2[c + 1];
                bfs[p * 37 + c]           = fmaxf(fmaf(d[mi][ni][0] + bj0, gs, bb), 0.f);
                bfs[p * 37 + c + 1]       = fmaxf(fmaf(d[mi][ni][1] + bj1, gs, bb), 0.f);
                bfs[(p + 8) * 37 + c]     = fmaxf(fmaf(d[mi][ni][2] + bj0, gs, bb), 0.f);
                bfs[(p + 8) * 37 + c + 1] = fmaxf(fmaf(d[mi][ni][3] + bj1, gs, bb), 0.f);
            }
        }
    }
    __syncthreads();

    // dyn[m][l] = sum_k bfeat[m*6+k] * bases[k][l]
    const int pp = t >> 1;               // 0..255
    const int half = t & 1;
    const float* bf = bfs + pp * 37;
    const int rr = pp >> 6, pw = pp & 63;
    float* outp = g_dyn + (size_t)((((nb << 6) + h0 + rr) << 6) + pw) * 54;
    #pragma unroll
    for (int q = 0; q < 27; q++) {
        int idx = half * 27 + q;
        int m = idx / 9, l = idx % 9;
        float s = 0.f;
        #pragma unroll
        for (int k = 0; k < 6; k++) s = fmaf(bf[m * 6 + k], bss[k * 9 + l], s);
        outp[idx] = s;
    }
}

// ===========================================================================
// Kernel 3a: bases_out A -> g_A[65536][768] (tf32-rounded)  (passing)
// ===========================================================================
#define K3A_SSTR 199
#define K3A_SMEM (CIN * K3A_SSTR * 4)

__global__ __launch_bounds__(256, 2)
void k3a_kernel(const float* __restrict__ x) {
    extern __shared__ float sm[];
    float* slab = sm;

    const int t  = threadIdx.x;
    const int bx = blockIdx.x;
    const int nb = bx >> 6;
    const int h  = bx & 63;

    const float4* x4 = (const float4*)x;
    for (int idx = t; idx < 3 * 66 * 32; idx += 256) {
        int ci4 = idx & 31;
        int col = (idx >> 5) % 66;
        int r   = idx / (32 * 66);
        int hh  = h + r - 1, ww = col - 1;
        float4 v = make_float4(0.f, 0.f, 0.f, 0.f);
        if (hh >= 0 && hh < HH && ww >= 0 && ww < WW)
            v = x4[((((nb << 6) + hh) << 6) + ww) * 32 + ci4];
        int so = r * 66 + col;
        slab[(ci4 * 4 + 0) * K3A_SSTR + so] = v.x;
        slab[(ci4 * 4 + 1) * K3A_SSTR + so] = v.y;
        slab[(ci4 * 4 + 2) * K3A_SSTR + so] = v.z;
        slab[(ci4 * 4 + 3) * K3A_SSTR + so] = v.w;
    }
    __syncthreads();

    const int w    = t >> 5;
    const int lane = t & 31;

    for (int pp = 0; pp < 8; pp++) {
        const int p = (w << 3) + pp;
        const size_t pix = (size_t)(bx << 6) + p;
        const float* dp = g_dyn + pix * 54;
        float dv[54];
        #pragma unroll
        for (int i = 0; i < 54; i++) dv[i] = __ldg(dp + i);

        float* arow = g_A + pix * 768;
        #pragma unroll
        for (int j = 0; j < 4; j++) {
            const int ch = lane + (j << 5);
            float pt[9];
            #pragma unroll
            for (int l = 0; l < 9; l++) {
                const int f  = ch * 9 + l;
                const int cc = f & 127;
                const int pi = f >> 7;
                pt[l] = slab[cc * K3A_SSTR + (pi / 3) * 66 + (pi % 3) + p];
            }
            uint32_t ov[6];
            #pragma unroll
            for (int m = 0; m < 6; m++) {
                float s = 0.f;
                #pragma unroll
                for (int l = 0; l < 9; l++) s = fmaf(dv[m * 9 + l], pt[l], s);
                ov[m] = tf32_rna(s);
            }
            float2* dst = (float2*)(arow + ch * 6);
            dst[0] = make_float2(__uint_as_float(ov[0]), __uint_as_float(ov[1]));
            dst[1] = make_float2(__uint_as_float(ov[2]), __uint_as_float(ov[3]));
            dst[2] = make_float2(__uint_as_float(ov[4]), __uint_as_float(ov[5]));
        }
    }
}

// ===========================================================================
// Kernel 3b: mma.sync tf32 GEMM out[65536,256] = A x B^T + bias  (passing)
// grid = 512 (mt), block 512 (16 warps, 4m x 4n); block tile 128x256.
// ===========================================================================
#define K3B_STR  36
#define K3B_ACH  (128 * K3B_STR)
#define K3B_BCH  (256 * K3B_STR)
#define K3B_SMEM ((2 * K3B_ACH + 2 * K3B_BCH) * 4)

__global__ __launch_bounds__(512, 1)
void k3b_kernel(const float* __restrict__ bias, float* __restrict__ out) {
    extern __shared__ float sm[];
    float* As[2] = { sm,              sm + K3B_ACH };
    float* Bs[2] = { sm + 2 * K3B_ACH, sm + 2 * K3B_ACH + K3B_BCH };

    const int t    = threadIdx.x;
    const int mt   = blockIdx.x;
    const int wid  = t >> 5;
    const int lane = t & 31;
    const int g    = lane >> 2;
    const int tid4 = lane & 3;

    const float* Abase = g_A + (size_t)(mt << 7) * 768;

    for (int i = t; i < 1024; i += 512) {
        int row = i >> 3, seg = i & 7;
        cp_async16(As[0] + row * K3B_STR + seg * 4, Abase + row * 768 + seg * 4);
    }
    for (int i = t; i < 2048; i += 512) {
        int row = i >> 3, seg = i & 7;
        cp_async16(Bs[0] + row * K3B_STR + seg * 4, g_Bt + row * 768 + seg * 4);
    }
    cp_commit();

    const int wm = wid >> 2, wn = wid & 3;
    const int m0 = wm << 5, n0 = wn << 6;
    float d[2][8][4] = {};

    for (int kc = 0; kc < 24; kc++) {
        cp_wait<0>();
        __syncthreads();
        if (kc < 23) {
            const int nc = kc + 1, buf = nc & 1;
            const float* as = Abase + nc * 32;
            const float* bs = g_Bt + nc * 32;
            for (int i = t; i < 1024; i += 512) {
                int row = i >> 3, seg = i & 7;
                cp_async16(As[buf] + row * K3B_STR + seg * 4, as + row * 768 + seg * 4);
            }
            for (int i = t; i < 2048; i += 512) {
                int row = i >> 3, seg = i & 7;
                cp_async16(Bs[buf] + row * K3B_STR + seg * 4, bs + row * 768 + seg * 4);
            }
            cp_commit();
        }
        const float* Ac = As[kc & 1];
        const float* Bc = Bs[kc & 1];

        #pragma unroll
        for (int kt = 0; kt < 4; kt++) {
            const int k0 = kt << 3;
            uint32_t a[2][4], b[8][2];
            #pragma unroll
            for (int mi = 0; mi < 2; mi++) {
                const float* ap = Ac + (m0 + (mi << 4) + g) * K3B_STR + k0 + tid4;
                a[mi][0] = __float_as_uint(ap[0]);
                a[mi][1] = __float_as_uint(ap[8 * K3B_STR]);
                a[mi][2] = __float_as_uint(ap[4]);
                a[mi][3] = __float_as_uint(ap[8 * K3B_STR + 4]);
            }
            #pragma unroll
            for (int ni = 0; ni < 8; ni++) {
                const float* bp = Bc + (n0 + (ni << 3) + g) * K3B_STR + k0 + tid4;
                b[ni][0] = __float_as_uint(bp[0]);
                b[ni][1] = __float_as_uint(bp[4]);
            }
            #pragma unroll
            for (int mi = 0; mi < 2; mi++)
                #pragma unroll
                for (int ni = 0; ni < 8; ni++)
                    mma_tf32(d[mi][ni], a[mi], b[ni]);
        }
        __syncthreads();
    }

    const size_t rbase = (size_t)(mt << 7) + m0;
    const int    cbase = n0 + (tid4 << 1);
    #pragma unroll
    for (int mi = 0; mi < 2; mi++) {
        float* r0 = out + (rbase + (mi << 4) + g) * OO;
        float* r1 = r0 + 8 * OO;
        #pragma unroll
        for (int ni = 0; ni < 8; ni++) {
            const int c = cbase + (ni << 3);
            const float b0 = bias[c], b1 = bias[c + 1];
            *(float2*)(r0 + c) = make_float2(d[mi][ni][0] + b0, d[mi][ni][1] + b1);
            *(float2*)(r1 + c) = make_float2(d[mi][ni][2] + b0, d[mi][ni][3] + b1);
        }
    }
}

// ===========================================================================
extern "C" void kernel_launch(void* const* d_in, const int* in_sizes, int n_in,
                              void* d_out, int out_size) {
    const float* x      = (const float*)d_in[0];
    const float* w1     = (const float*)d_in[1];
    const float* b1     = (const float*)d_in[2];
    const float* gamma1 = (const float*)d_in[3];
    const float* beta1  = (const float*)d_in[4];
    const float* w2     = (const float*)d_in[5];
    const float* b2     = (const float*)d_in[6];
    const float* gamma2 = (const float*)d_in[7];
    const float* beta2  = (const float*)d_in[8];
    const float* bases  = (const float*)d_in[9];
    const float* coef   = (const float*)d_in[10];
    const float* bias   = (const float*)d_in[11];
    float* out = (float*)d_out;

    cudaFuncSetAttribute(conv1_kernel, cudaFuncAttributeMaxDynamicSharedMemorySize, C1_SMEM);
    cudaFuncSetAttribute(conv2_kernel, cudaFuncAttributeMaxDynamicSharedMemorySize, C2_SMEM);
    cudaFuncSetAttribute(k3a_kernel,   cudaFuncAttributeMaxDynamicSharedMemorySize, K3A_SMEM);
    cudaFuncSetAttribute(k3b_kernel,   cudaFuncAttributeMaxDynamicSharedMemorySize, K3B_SMEM);

    prepW_kernel <<<576, 128>>>(w1);
    prepW2_kernel<<<48,  576>>>(w2);
    prepB_kernel <<<OO,  256>>>(coef);
    conv1_kernel<<<NB * HH / 2, 512, C1_SMEM>>>(x, b1, gamma1, beta1);
    conv2_kernel<<<NB * HH / 4, 512, C2_SMEM>>>(b2, gamma2, beta2, bases);
    k3a_kernel  <<<NB * HH,     256, K3A_SMEM>>>(x);
    k3b_kernel  <<<512,         512, K3B_SMEM>>>(bias, out);
}